// round 6
// baseline (speedup 1.0000x reference)
#include <cuda_runtime.h>
#include <math.h>

#define E 1024
#define H 16
#define D 64
#define B 4
#define S 1024
#define NROWS (B*S)     // 4096
#define FFDIM 2048
#define ATT_SCALE 0.03125f    // 1/sqrt(1024)

// ------------------------- scratch (no allocations allowed) -----------------
__device__ float g_qp[NROWS * E];
__device__ float g_kp[NROWS * E];
__device__ float g_vp[NROWS * E];
__device__ float g_attn[NROWS * E];
__device__ float g_att[NROWS * E];
__device__ float g_h[NROWS * E];
__device__ float g_g1[NROWS * FFDIM];
__device__ float g_ff[NROWS * E];
__device__ int   g_mq[NROWS];
__device__ int   g_mk[NROWS];

// ------------------------- mask canonicalization ----------------------------
__global__ void mask_convert_kernel(const void* __restrict__ raw,
                                    int* __restrict__ out, int n) {
    __shared__ int s_big, s_nonal;
    if (threadIdx.x == 0) { s_big = 0; s_nonal = 0; }
    __syncthreads();
    const unsigned char* p = (const unsigned char*)raw;
    int big = 0, nonal = 0;
    for (int i = threadIdx.x; i < n; i += blockDim.x) {
        unsigned char v = p[i];
        if (v > 1) big = 1;
        if ((i & 3) != 0 && v != 0) nonal = 1;
    }
    if (big)   atomicOr(&s_big, 1);
    if (nonal) atomicOr(&s_nonal, 1);
    __syncthreads();
    int kind = s_big ? 2 : (s_nonal ? 1 : 0);
    for (int i = threadIdx.x; i < n; i += blockDim.x) {
        int v;
        if (kind == 2)      v = (((const float*)raw)[i] != 0.0f);
        else if (kind == 1) v = (p[i] != 0);
        else                v = (((const int*)raw)[i] != 0);
        out[i] = v;
    }
}

// ------------------------- tf32 helpers --------------------------------------
__device__ __forceinline__ unsigned f2tf(float f) {
    unsigned u;
    asm("cvt.rna.tf32.f32 %0, %1;" : "=r"(u) : "f"(f));
    return u;
}

__device__ __forceinline__ void mma8(float c[4], const unsigned a[4], const unsigned b[2]) {
    asm volatile(
        "mma.sync.aligned.m16n8k8.row.col.f32.tf32.tf32.f32 "
        "{%0,%1,%2,%3}, {%4,%5,%6,%7}, {%8,%9}, {%0,%1,%2,%3};"
        : "+f"(c[0]), "+f"(c[1]), "+f"(c[2]), "+f"(c[3])
        : "r"(a[0]), "r"(a[1]), "r"(a[2]), "r"(a[3]), "r"(b[0]), "r"(b[1]));
}

__device__ __forceinline__ void ldsm4(unsigned r[4], unsigned saddr) {
    asm volatile("ldmatrix.sync.aligned.m8n8.x4.shared.b16 {%0,%1,%2,%3}, [%4];"
                 : "=r"(r[0]), "=r"(r[1]), "=r"(r[2]), "=r"(r[3]) : "r"(saddr));
}

__device__ __forceinline__ void cp16(void* smem, const void* g) {
    unsigned s = (unsigned)__cvta_generic_to_shared(smem);
    asm volatile("cp.async.cg.shared.global [%0], [%1], 16;\n" :: "r"(s), "l"(g));
}
__device__ __forceinline__ void cp_commit() { asm volatile("cp.async.commit_group;\n"); }
template<int N> __device__ __forceinline__ void cp_wait() {
    asm volatile("cp.async.wait_group %0;\n" :: "n"(N));
}

// ------------------------- tf32 tensor-core GEMM -----------------------------
// C[M,N] = A[M,K] @ Bm[K,N] (+bias) (+quick_gelu). Row-major.
// 128x128 tile, BK=16, 8 warps (2M x 4N), 64x32 per warp, m16n8k8 tf32.
// 4-stage circular cp.async pipeline (dynamic smem, 74.7KB), ONE
// __syncthreads per iteration; empty commit_groups in the tail keep the
// wait_group<2> arithmetic exact. RNA tf32 conversion at fragment
// consumption (numerics identical to prior rounds).
// A smem [m][k] stride 20 (LDSM conflict-free); B smem [k][n] stride 132.
#define ASTR 20
#define BSTR 132
#define GSTAGES 4
#define STAGE_F (128 * ASTR + 16 * BSTR)           // 4672 floats per stage
#define GEMM_SMEM_BYTES (GSTAGES * STAGE_F * 4)    // 74752 B

template<int EPI>
__global__ __launch_bounds__(256, 2)
void tc_gemm(const float* __restrict__ A, const float* __restrict__ Bm,
             const float* __restrict__ bias, float* __restrict__ C,
             int M, int N, int K) {
    extern __shared__ float smem[];
    const int tid = threadIdx.x;
    const int bm = blockIdx.y * 128, bn = blockIdx.x * 128;
    const int warp = tid >> 5, lane = tid & 31;
    const int wm = (warp & 1) * 64;
    const int wn = (warp >> 1) * 32;
    const int g = lane >> 2, t4 = lane & 3;

    // ldmatrix lane geometry
    const int lrow = (lane & 7) + ((lane & 8) ? 8 : 0);
    const int lkof = (lane & 16) ? 4 : 0;

    // loader coords
    const int am = tid >> 2, ak = (tid & 3) * 4;          // A rows am, am+64
    const int br = tid >> 4, bc = (tid & 15) * 8;         // B row br, cols bc..bc+7
    const float* Aptr = A + (size_t)(bm + am) * K + ak;
    const float* Bptr = Bm + (size_t)br * N + bn + bc;

    const unsigned sbase = (unsigned)__cvta_generic_to_shared(smem);

    float c[4][4][4];
#pragma unroll
    for (int i = 0; i < 4; i++)
#pragma unroll
        for (int j = 0; j < 4; j++)
#pragma unroll
            for (int r = 0; r < 4; r++) c[i][j][r] = 0.0f;

    auto load_stage = [&](int buf, int tI) {
        float* As = smem + buf * STAGE_F;
        float* Bs = As + 128 * ASTR;
        const float* Ap = Aptr + tI * 16;
        const float* Bp = Bptr + (size_t)tI * 16 * N;
        cp16(&As[am * ASTR + ak], Ap);
        cp16(&As[(am + 64) * ASTR + ak], Ap + (size_t)64 * K);
        cp16(&Bs[br * BSTR + bc], Bp);
        cp16(&Bs[br * BSTR + bc + 4], Bp + 4);
    };

    const int T = K / 16;
    // prologue: stages 0..2
#pragma unroll
    for (int s = 0; s < GSTAGES - 1; s++) {
        load_stage(s, s);
        cp_commit();
    }

    for (int tI = 0; tI < T; tI++) {
        const int buf = tI & (GSTAGES - 1);
        cp_wait<GSTAGES - 2>();      // stage tI resident (2 newer groups may fly)
        __syncthreads();             // also protects buffer (tI-1)&3 from overwrite
        if (tI + GSTAGES - 1 < T)
            load_stage((tI + GSTAGES - 1) & (GSTAGES - 1), tI + GSTAGES - 1);
        cp_commit();                 // empty group in tail keeps counts exact

        const float* As = smem + buf * STAGE_F;
        const float* Bs = As + 128 * ASTR;
        const unsigned sA = sbase + 4u * (buf * STAGE_F);
#pragma unroll
        for (int step = 0; step < 2; step++) {
            const int kk = step * 8;
            unsigned af[4][4], bf[4][2];
#pragma unroll
            for (int i = 0; i < 4; i++) {
                const int m0 = wm + i * 16;
                unsigned addr = sA + 4u * ((m0 + lrow) * ASTR + kk + lkof);
                unsigned raw[4];
                ldsm4(raw, addr);
                af[i][0] = f2tf(__uint_as_float(raw[0]));
                af[i][1] = f2tf(__uint_as_float(raw[1]));
                af[i][2] = f2tf(__uint_as_float(raw[2]));
                af[i][3] = f2tf(__uint_as_float(raw[3]));
            }
#pragma unroll
            for (int j = 0; j < 4; j++) {
                const int n0 = wn + j * 8 + g;
                bf[j][0] = f2tf(Bs[(kk + t4) * BSTR + n0]);
                bf[j][1] = f2tf(Bs[(kk + t4 + 4) * BSTR + n0]);
            }
#pragma unroll
            for (int i = 0; i < 4; i++)
#pragma unroll
                for (int j = 0; j < 4; j++)
                    mma8(c[i][j], af[i], bf[j]);
        }
    }

#pragma unroll
    for (int i = 0; i < 4; i++) {
#pragma unroll
        for (int j = 0; j < 4; j++) {
            const int row0 = bm + wm + i * 16 + g;
            const int col = bn + wn + j * 8 + 2 * t4;
            float v0 = c[i][j][0], v1 = c[i][j][1], v2 = c[i][j][2], v3 = c[i][j][3];
            if (EPI >= 1) {
                float b0 = bias[col], b1 = bias[col + 1];
                v0 += b0; v1 += b1; v2 += b0; v3 += b1;
            }
            if (EPI == 2) {
                v0 *= 1.0f / (1.0f + __expf(-1.702f * v0));
                v1 *= 1.0f / (1.0f + __expf(-1.702f * v1));
                v2 *= 1.0f / (1.0f + __expf(-1.702f * v2));
                v3 *= 1.0f / (1.0f + __expf(-1.702f * v3));
            }
            float2 p0 = {v0, v1}, p1 = {v2, v3};
            *(float2*)(C + (size_t)row0 * N + col) = p0;
            *(float2*)(C + (size_t)(row0 + 8) * N + col) = p1;
        }
    }
}

// ------------------------- tensor-core flash attention -----------------------
#define KSTR 68
#define VSTR 72
#define PSTR 36
#define KB   32

__global__ __launch_bounds__(128)
void attn_tc_kernel(const float* __restrict__ qp, const float* __restrict__ kp,
                    const float* __restrict__ vp, const int* __restrict__ mq,
                    const int* __restrict__ mk, float* __restrict__ out) {
    __shared__ float Ks[2][KB * KSTR];
    __shared__ float Vs[2][KB * VSTR];
    __shared__ float kmS[2][KB];
    __shared__ unsigned Pw[4][16 * PSTR];

    const int b = blockIdx.z, h = blockIdx.y;
    const int q0 = blockIdx.x * 64;
    const int tid = threadIdx.x;
    const int w = tid >> 5, lane = tid & 31;
    const int g = lane >> 2, t4 = lane & 3;

    unsigned qa[8][4];
    {
        const float* Qr0 = qp + (size_t)(b * S + q0 + w * 16 + g) * E + h * D;
        const float* Qr1 = Qr0 + (size_t)8 * E;
#pragma unroll
        for (int s = 0; s < 8; s++) {
            qa[s][0] = f2tf(Qr0[8 * s + t4]);
            qa[s][1] = f2tf(Qr1[8 * s + t4]);
            qa[s][2] = f2tf(Qr0[8 * s + t4 + 4]);
            qa[s][3] = f2tf(Qr1[8 * s + t4 + 4]);
        }
    }

    float oacc[8][4];
#pragma unroll
    for (int n = 0; n < 8; n++)
#pragma unroll
        for (int r = 0; r < 4; r++) oacc[n][r] = 0.0f;
    float l0 = 0.0f, l1 = 0.0f;

    auto load_tiles = [&](int kt, int buf) {
#pragma unroll
        for (int c = 0; c < 4; c++) {
            int slot = tid + 128 * c;
            int key = slot >> 4, c4 = (slot & 15) * 4;
            const float* gk = kp + (size_t)(b * S + kt + key) * E + h * D + c4;
            const float* gv = vp + (size_t)(b * S + kt + key) * E + h * D + c4;
            cp16(&Ks[buf][key * KSTR + c4], gk);
            cp16(&Vs[buf][key * VSTR + c4], gv);
        }
        if (tid < KB) kmS[buf][tid] = mk[b * S + kt + tid] ? 1.0f : 0.0f;
    };

    load_tiles(0, 0);
    cp_commit();

    for (int kb = 0; kb < S / KB; kb++) {
        const int buf = kb & 1;
        if (kb + 1 < S / KB) {
            load_tiles((kb + 1) * KB, buf ^ 1);
            cp_commit();
            cp_wait<1>();
        } else {
            cp_wait<0>();
        }
        __syncthreads();

        float sc[4][4];
#pragma unroll
        for (int j = 0; j < 4; j++)
#pragma unroll
            for (int r = 0; r < 4; r++) sc[j][r] = 0.0f;
#pragma unroll
        for (int s = 0; s < 8; s++) {
#pragma unroll
            for (int j = 0; j < 4; j++) {
                unsigned bf[2];
                bf[0] = f2tf(Ks[buf][(8 * j + g) * KSTR + 8 * s + t4]);
                bf[1] = f2tf(Ks[buf][(8 * j + g) * KSTR + 8 * s + t4 + 4]);
                mma8(sc[j], qa[s], bf);
            }
        }

#pragma unroll
        for (int j = 0; j < 4; j++) {
            const int c0 = 8 * j + 2 * t4;
            float m0 = kmS[buf][c0], m1 = kmS[buf][c0 + 1];
            float p0 = __expf(sc[j][0] * ATT_SCALE) * m0;
            float p1 = __expf(sc[j][1] * ATT_SCALE) * m1;
            float p2 = __expf(sc[j][2] * ATT_SCALE) * m0;
            float p3 = __expf(sc[j][3] * ATT_SCALE) * m1;
            l0 += p0 + p1;
            l1 += p2 + p3;
            Pw[w][g * PSTR + c0]           = f2tf(p0);
            Pw[w][g * PSTR + c0 + 1]       = f2tf(p1);
            Pw[w][(g + 8) * PSTR + c0]     = f2tf(p2);
            Pw[w][(g + 8) * PSTR + c0 + 1] = f2tf(p3);
        }
        __syncwarp();

#pragma unroll
        for (int s = 0; s < 4; s++) {
            unsigned pa[4];
            pa[0] = Pw[w][g * PSTR + 8 * s + t4];
            pa[1] = Pw[w][(g + 8) * PSTR + 8 * s + t4];
            pa[2] = Pw[w][g * PSTR + 8 * s + t4 + 4];
            pa[3] = Pw[w][(g + 8) * PSTR + 8 * s + t4 + 4];
#pragma unroll
            for (int n = 0; n < 8; n++) {
                unsigned bf[2];
                bf[0] = f2tf(Vs[buf][(8 * s + t4) * VSTR + 8 * n + g]);
                bf[1] = f2tf(Vs[buf][(8 * s + t4 + 4) * VSTR + 8 * n + g]);
                mma8(oacc[n], pa, bf);
            }
        }
        __syncthreads();
    }

    l0 += __shfl_xor_sync(0xffffffffu, l0, 1);
    l0 += __shfl_xor_sync(0xffffffffu, l0, 2);
    l1 += __shfl_xor_sync(0xffffffffu, l1, 1);
    l1 += __shfl_xor_sync(0xffffffffu, l1, 2);

    const int row0 = b * S + q0 + w * 16 + g;
    const float inv0 = mq[row0] ? 1.0f / l0 : 0.0f;
    const float inv1 = mq[row0 + 8] ? 1.0f / l1 : 0.0f;
    float* o0 = out + (size_t)row0 * E + h * D;
    float* o1 = o0 + (size_t)8 * E;
#pragma unroll
    for (int n = 0; n < 8; n++) {
        const int c0 = 8 * n + 2 * t4;
        float2 v0 = {oacc[n][0] * inv0, oacc[n][1] * inv0};
        float2 v1 = {oacc[n][2] * inv1, oacc[n][3] * inv1};
        *(float2*)(o0 + c0) = v0;
        *(float2*)(o1 + c0) = v1;
    }
}

// ------------------------- layernorm + mask + residual -----------------------
template<int MODE>
__global__ __launch_bounds__(256)
void ln_kernel(const float* __restrict__ x, const float* __restrict__ res,
               const float* __restrict__ g, const float* __restrict__ bb,
               const int* __restrict__ mask, float* __restrict__ out) {
    __shared__ float s1[256], s2[256];
    const int row = blockIdx.x;
    const int tid = threadIdx.x;
    const float* xr = x + (size_t)row * E;
    const float* rr = res + (size_t)row * E;
    float v[4];
    float s = 0.0f, sq = 0.0f;
#pragma unroll
    for (int i = 0; i < 4; i++) {
        int c = tid + i * 256;
        float t = xr[c];
        if (MODE == 1) t += rr[c];
        v[i] = t; s += t; sq += t * t;
    }
    s1[tid] = s; s2[tid] = sq;
    __syncthreads();
    for (int off = 128; off > 0; off >>= 1) {
        if (tid < off) { s1[tid] += s1[tid + off]; s2[tid] += s2[tid + off]; }
        __syncthreads();
    }
    float mu = s1[0] * (1.0f / E);
    float var = s2[0] * (1.0f / E) - mu * mu;
    float rstd = rsqrtf(var + 1e-5f);
    float mkf = mask[row] ? 1.0f : 0.0f;
#pragma unroll
    for (int i = 0; i < 4; i++) {
        int c = tid + i * 256;
        float y = (v[i] - mu) * rstd * g[c] + bb[c];
        if (MODE == 0) out[(size_t)row * E + c] = y * mkf + rr[c];
        else           out[(size_t)row * E + c] = y * mkf;
    }
}

// ------------------------- launch -------------------------------------------
extern "C" void kernel_launch(void* const* d_in, const int* in_sizes, int n_in,
                              void* d_out, int out_size) {
    const float* value = (const float*)d_in[0];
    const float* key   = (const float*)d_in[1];
    const float* query = (const float*)d_in[2];
    const void*  mask_k_raw = d_in[3];
    const void*  mask_q_raw = d_in[4];
    const float* Wv = (const float*)d_in[5];
    const float* Wk = (const float*)d_in[6];
    const float* Wq = (const float*)d_in[7];
    const float* Wo = (const float*)d_in[8];
    const float* ln0_g = (const float*)d_in[9];
    const float* ln0_b = (const float*)d_in[10];
    const float* W1 = (const float*)d_in[11];
    const float* b1 = (const float*)d_in[12];
    const float* W2 = (const float*)d_in[13];
    const float* b2 = (const float*)d_in[14];
    const float* ln1_g = (const float*)d_in[15];
    const float* ln1_b = (const float*)d_in[16];
    float* out = (float*)d_out;

    float *qp, *kp, *vp, *attn, *att, *hbuf, *g1, *ff;
    int *mq, *mk;
    cudaGetSymbolAddress((void**)&qp,   g_qp);
    cudaGetSymbolAddress((void**)&kp,   g_kp);
    cudaGetSymbolAddress((void**)&vp,   g_vp);
    cudaGetSymbolAddress((void**)&attn, g_attn);
    cudaGetSymbolAddress((void**)&att,  g_att);
    cudaGetSymbolAddress((void**)&hbuf, g_h);
    cudaGetSymbolAddress((void**)&g1,   g_g1);
    cudaGetSymbolAddress((void**)&ff,   g_ff);
    cudaGetSymbolAddress((void**)&mq,   g_mq);
    cudaGetSymbolAddress((void**)&mk,   g_mk);

    // raise dynamic smem limit (idempotent; attribute set, not an allocation)
    cudaFuncSetAttribute(tc_gemm<0>, cudaFuncAttributeMaxDynamicSharedMemorySize, GEMM_SMEM_BYTES);
    cudaFuncSetAttribute(tc_gemm<1>, cudaFuncAttributeMaxDynamicSharedMemorySize, GEMM_SMEM_BYTES);
    cudaFuncSetAttribute(tc_gemm<2>, cudaFuncAttributeMaxDynamicSharedMemorySize, GEMM_SMEM_BYTES);

    mask_convert_kernel<<<1, 256>>>(mask_k_raw, mk, NROWS);
    mask_convert_kernel<<<1, 256>>>(mask_q_raw, mq, NROWS);

    dim3 gE(E / 128, NROWS / 128);        // 8 x 32
    dim3 gF(FFDIM / 128, NROWS / 128);    // 16 x 32

    tc_gemm<0><<<gE, 256, GEMM_SMEM_BYTES>>>(query, Wq, nullptr, qp, NROWS, E, E);
    tc_gemm<0><<<gE, 256, GEMM_SMEM_BYTES>>>(key,   Wk, nullptr, kp, NROWS, E, E);
    tc_gemm<0><<<gE, 256, GEMM_SMEM_BYTES>>>(value, Wv, nullptr, vp, NROWS, E, E);

    attn_tc_kernel<<<dim3(S / 64, H, B), 128>>>(qp, kp, vp, mq, mk, attn);

    tc_gemm<0><<<gE, 256, GEMM_SMEM_BYTES>>>(attn, Wo, nullptr, att, NROWS, E, E);

    ln_kernel<0><<<NROWS, 256>>>(att, query, ln0_g, ln0_b, mq, hbuf);

    tc_gemm<2><<<gF, 256, GEMM_SMEM_BYTES>>>(hbuf, W1, b1, g1, NROWS, FFDIM, E);
    tc_gemm<1><<<gE, 256, GEMM_SMEM_BYTES>>>(g1, W2, b2, ff, NROWS, E, FFDIM);

    ln_kernel<1><<<NROWS, 256>>>(ff, query, ln1_g, ln1_b, mq, out);
}

// round 8
// speedup vs baseline: 1.9946x; 1.9946x over previous
#include <cuda_runtime.h>
#include <cuda_fp16.h>
#include <math.h>

#define E 1024
#define H 16
#define D 64
#define B 4
#define S 1024
#define NROWS (B*S)     // 4096
#define FFDIM 2048
#define ATT_SCALE 0.03125f    // 1/sqrt(1024)

// ------------------------- scratch (no allocations allowed) -----------------
__device__ __half g_qh[NROWS * E];      // fp16 copies of inputs
__device__ __half g_kh[NROWS * E];
__device__ __half g_vh[NROWS * E];
__device__ __half g_Wqh[E * E];
__device__ __half g_Wkh[E * E];
__device__ __half g_Wvh[E * E];
__device__ __half g_Woh[E * E];
__device__ __half g_W1h[E * FFDIM];
__device__ __half g_W2h[FFDIM * E];
__device__ __half g_qph[NROWS * E];     // projections (fp16)
__device__ __half g_kph[NROWS * E];
__device__ __half g_vph[NROWS * E];
__device__ __half g_attnh[NROWS * E];   // attention output (fp16)
__device__ float  g_att[NROWS * E];     // Wo output (fp32, -> LN)
__device__ __half g_hh[NROWS * E];      // LN0 + residual (fp16, -> W1)
__device__ __half g_g1h[NROWS * FFDIM]; // gelu(W1) (fp16, -> W2)
__device__ float  g_ff[NROWS * E];      // W2 output (fp32, -> LN)
__device__ int    g_mq[NROWS];
__device__ int    g_mk[NROWS];

// ------------------------- mask canonicalization ----------------------------
__global__ void mask_convert_kernel(const void* __restrict__ raw,
                                    int* __restrict__ out, int n) {
    __shared__ int s_big, s_nonal;
    if (threadIdx.x == 0) { s_big = 0; s_nonal = 0; }
    __syncthreads();
    const unsigned char* p = (const unsigned char*)raw;
    int big = 0, nonal = 0;
    for (int i = threadIdx.x; i < n; i += blockDim.x) {
        unsigned char v = p[i];
        if (v > 1) big = 1;
        if ((i & 3) != 0 && v != 0) nonal = 1;
    }
    if (big)   atomicOr(&s_big, 1);
    if (nonal) atomicOr(&s_nonal, 1);
    __syncthreads();
    int kind = s_big ? 2 : (s_nonal ? 1 : 0);
    for (int i = threadIdx.x; i < n; i += blockDim.x) {
        int v;
        if (kind == 2)      v = (((const float*)raw)[i] != 0.0f);
        else if (kind == 1) v = (p[i] != 0);
        else                v = (((const int*)raw)[i] != 0);
        out[i] = v;
    }
}

// ------------------------- fp32 -> fp16 conversion ---------------------------
__global__ __launch_bounds__(256)
void f2h_kernel(const float* __restrict__ in, __half* __restrict__ out, int n4) {
    int i = blockIdx.x * blockDim.x + threadIdx.x;
    int stride = gridDim.x * blockDim.x;
    for (; i < n4; i += stride) {
        float4 v = ((const float4*)in)[i];
        __half2* o = (__half2*)out + 2 * i;
        o[0] = __floats2half2_rn(v.x, v.y);
        o[1] = __floats2half2_rn(v.z, v.w);
    }
}

// ------------------------- mma / ldmatrix helpers ----------------------------
__device__ __forceinline__ unsigned h2u(__half2 h) {
    union { __half2 h; unsigned u; } cvt;
    cvt.h = h;
    return cvt.u;
}

__device__ __forceinline__ void mma16(float c[4], const unsigned a[4], const unsigned b[2]) {
    asm volatile(
        "mma.sync.aligned.m16n8k16.row.col.f32.f16.f16.f32 "
        "{%0,%1,%2,%3}, {%4,%5,%6,%7}, {%8,%9}, {%0,%1,%2,%3};"
        : "+f"(c[0]), "+f"(c[1]), "+f"(c[2]), "+f"(c[3])
        : "r"(a[0]), "r"(a[1]), "r"(a[2]), "r"(a[3]), "r"(b[0]), "r"(b[1]));
}

__device__ __forceinline__ void ldsm4(unsigned r[4], unsigned saddr) {
    asm volatile("ldmatrix.sync.aligned.m8n8.x4.shared.b16 {%0,%1,%2,%3}, [%4];"
                 : "=r"(r[0]), "=r"(r[1]), "=r"(r[2]), "=r"(r[3]) : "r"(saddr));
}
__device__ __forceinline__ void ldsm4t(unsigned r[4], unsigned saddr) {
    asm volatile("ldmatrix.sync.aligned.m8n8.x4.trans.shared.b16 {%0,%1,%2,%3}, [%4];"
                 : "=r"(r[0]), "=r"(r[1]), "=r"(r[2]), "=r"(r[3]) : "r"(saddr));
}

__device__ __forceinline__ void cp16(void* smem, const void* g) {
    unsigned s = (unsigned)__cvta_generic_to_shared(smem);
    asm volatile("cp.async.cg.shared.global [%0], [%1], 16;\n" :: "r"(s), "l"(g));
}
__device__ __forceinline__ void cp_commit() { asm volatile("cp.async.commit_group;\n"); }
template<int N> __device__ __forceinline__ void cp_wait() {
    asm volatile("cp.async.wait_group %0;\n" :: "n"(N));
}

// ------------------------- fp16 tensor-core GEMM -----------------------------
// C[M,N] = A[M,K] @ Bm[K,N] (+bias fp32) (+quick_gelu). A,Bm fp16 row-major,
// accumulate fp32, C is OutT (half or float).
// 128x128 tile, BK=32, 8 warps (2M x 4N), 64x32/warp, m16n8k16.
// A smem [m][k] stride 40 halfs (80B: LDSM conflict-free);
// B smem [k][n] stride 136 halfs (272B: LDSM.T conflict-free).
// 4-stage circular cp.async pipeline, one __syncthreads per iteration.
#define ASTR 40
#define BSTR 136
#define GSTAGES 4
#define STAGE_H (128 * ASTR + 32 * BSTR)           // 9472 halfs per stage
#define GEMM_SMEM_BYTES (GSTAGES * STAGE_H * 2)    // 75776 B

template<int EPI, typename OutT>
__global__ __launch_bounds__(256, 2)
void tc_gemm(const __half* __restrict__ A, const __half* __restrict__ Bm,
             const float* __restrict__ bias, OutT* __restrict__ C,
             int M, int N, int K) {
    extern __shared__ __half smem[];
    const int tid = threadIdx.x;
    const int bm = blockIdx.y * 128, bn = blockIdx.x * 128;
    const int warp = tid >> 5, lane = tid & 31;
    const int wm = (warp & 1) * 64;
    const int wn = (warp >> 1) * 32;
    const int g = lane >> 2, t4 = lane & 3;
    const int l16 = lane & 15, lhi = (lane & 16) ? 8 : 0;

    // loader coords: A 128x32 halfs (2 thr/row, 16 halfs each); B 32x128 (8 thr/row)
    const int am = tid >> 1, ac = (tid & 1) * 16;
    const int br = tid >> 3, bc = (tid & 7) * 16;
    const __half* Aptr = A + (size_t)(bm + am) * K + ac;
    const __half* Bptr = Bm + (size_t)br * N + bn + bc;

    const unsigned sbase = (unsigned)__cvta_generic_to_shared(smem);

    float c[4][4][4];
#pragma unroll
    for (int i = 0; i < 4; i++)
#pragma unroll
        for (int j = 0; j < 4; j++)
#pragma unroll
            for (int r = 0; r < 4; r++) c[i][j][r] = 0.0f;

    auto load_stage = [&](int buf, int tI) {
        __half* As = smem + buf * STAGE_H;
        __half* Bs = As + 128 * ASTR;
        const __half* Ap = Aptr + tI * 32;
        const __half* Bp = Bptr + (size_t)tI * 32 * N;
        cp16(&As[am * ASTR + ac], Ap);
        cp16(&As[am * ASTR + ac + 8], Ap + 8);
        cp16(&Bs[br * BSTR + bc], Bp);
        cp16(&Bs[br * BSTR + bc + 8], Bp + 8);
    };

    const int T = K / 32;
#pragma unroll
    for (int s = 0; s < GSTAGES - 1; s++) {
        load_stage(s, s);
        cp_commit();
    }

    for (int tI = 0; tI < T; tI++) {
        const int buf = tI & (GSTAGES - 1);
        cp_wait<GSTAGES - 2>();
        __syncthreads();
        if (tI + GSTAGES - 1 < T)
            load_stage((tI + GSTAGES - 1) & (GSTAGES - 1), tI + GSTAGES - 1);
        cp_commit();

        const unsigned sA = sbase + 2u * (buf * STAGE_H);
        const unsigned sB = sA + 2u * (128 * ASTR);
#pragma unroll
        for (int step = 0; step < 2; step++) {
            const int k0 = step * 16;
            unsigned af[4][4], bf[4][2];
#pragma unroll
            for (int i = 0; i < 4; i++) {
                unsigned addr = sA + 2u * ((wm + i * 16 + l16) * ASTR + k0 + lhi);
                ldsm4(af[i], addr);
            }
#pragma unroll
            for (int jp = 0; jp < 2; jp++) {
                unsigned addr = sB + 2u * ((k0 + l16) * BSTR + wn + jp * 16 + lhi);
                unsigned r[4];
                ldsm4t(r, addr);
                bf[2 * jp][0] = r[0];     bf[2 * jp][1] = r[1];
                bf[2 * jp + 1][0] = r[2]; bf[2 * jp + 1][1] = r[3];
            }
#pragma unroll
            for (int i = 0; i < 4; i++)
#pragma unroll
                for (int j = 0; j < 4; j++)
                    mma16(c[i][j], af[i], bf[j]);
        }
    }

#pragma unroll
    for (int i = 0; i < 4; i++) {
#pragma unroll
        for (int j = 0; j < 4; j++) {
            const int row0 = bm + wm + i * 16 + g;
            const int col = bn + wn + j * 8 + 2 * t4;
            float v0 = c[i][j][0], v1 = c[i][j][1], v2 = c[i][j][2], v3 = c[i][j][3];
            if (EPI >= 1) {
                float b0 = bias[col], b1 = bias[col + 1];
                v0 += b0; v1 += b1; v2 += b0; v3 += b1;
            }
            if (EPI == 2) {
                v0 *= 1.0f / (1.0f + __expf(-1.702f * v0));
                v1 *= 1.0f / (1.0f + __expf(-1.702f * v1));
                v2 *= 1.0f / (1.0f + __expf(-1.702f * v2));
                v3 *= 1.0f / (1.0f + __expf(-1.702f * v3));
            }
            if (sizeof(OutT) == 2) {
                *(__half2*)((__half*)C + (size_t)row0 * N + col) = __floats2half2_rn(v0, v1);
                *(__half2*)((__half*)C + (size_t)(row0 + 8) * N + col) = __floats2half2_rn(v2, v3);
            } else {
                float2 p0 = {v0, v1}, p1 = {v2, v3};
                *(float2*)((float*)C + (size_t)row0 * N + col) = p0;
                *(float2*)((float*)C + (size_t)(row0 + 8) * N + col) = p1;
            }
        }
    }
}

// ------------------------- fp16 tensor-core flash attention ------------------
// Block: 64 q x (b,h). 4 warps x 16 q rows. KB=32 keys double-buffered.
// Q@K^T: K [key][d] smem, non-trans ldsm -> B frags. P packed to half2 in
// registers (S c-frag layout == P a-frag layout). P@V: V [key][d] smem,
// trans ldsm -> B frags. All smem rows stride 72 halfs (144B, conflict-free).
#define KVSTR 72
#define KB 32

__global__ __launch_bounds__(128)
void attn_tc_kernel(const __half* __restrict__ qp, const __half* __restrict__ kp,
                    const __half* __restrict__ vp, const int* __restrict__ mq,
                    const int* __restrict__ mk, __half* __restrict__ out) {
    __shared__ __half Ks[2][KB * KVSTR];
    __shared__ __half Vs[2][KB * KVSTR];
    __shared__ float kmS[2][KB];

    const int b = blockIdx.z, h = blockIdx.y;
    const int q0 = blockIdx.x * 64;
    const int tid = threadIdx.x;
    const int w = tid >> 5, lane = tid & 31;
    const int g = lane >> 2, t4 = lane & 3;
    const int l16 = lane & 15, lhi = (lane & 16) ? 8 : 0;
    const int l8 = lane & 7, lm = ((lane & 8) ? 8 : 0), ln16 = (lane & 16) ? 8 : 0;

    const unsigned sK0 = (unsigned)__cvta_generic_to_shared(&Ks[0][0]);
    const unsigned sK1 = (unsigned)__cvta_generic_to_shared(&Ks[1][0]);
    const unsigned sV0 = (unsigned)__cvta_generic_to_shared(&Vs[0][0]);
    const unsigned sV1 = (unsigned)__cvta_generic_to_shared(&Vs[1][0]);

    // Q fragments (persistent): rows q0+16w+g (+8); kstep s covers d=16s..16s+15
    unsigned qa[4][4];
    {
        const __half* Qr0 = qp + (size_t)(b * S + q0 + w * 16 + g) * E + h * D;
        const __half* Qr1 = Qr0 + (size_t)8 * E;
#pragma unroll
        for (int s = 0; s < 4; s++) {
            qa[s][0] = *(const unsigned*)&Qr0[16 * s + 2 * t4];
            qa[s][1] = *(const unsigned*)&Qr1[16 * s + 2 * t4];
            qa[s][2] = *(const unsigned*)&Qr0[16 * s + 8 + 2 * t4];
            qa[s][3] = *(const unsigned*)&Qr1[16 * s + 8 + 2 * t4];
        }
    }

    float oacc[8][4];
#pragma unroll
    for (int n = 0; n < 8; n++)
#pragma unroll
        for (int r = 0; r < 4; r++) oacc[n][r] = 0.0f;
    float l0 = 0.0f, l1 = 0.0f;

    auto load_tiles = [&](int kt, int buf) {
        // K/V tile 32x64 halfs = 4KB each: 128 threads x 2 chunks per tensor
        int key = tid >> 2, c8 = (tid & 3) * 16;
        const __half* gk = kp + (size_t)(b * S + kt + key) * E + h * D + c8;
        const __half* gv = vp + (size_t)(b * S + kt + key) * E + h * D + c8;
        cp16(&Ks[buf][key * KVSTR + c8], gk);
        cp16(&Ks[buf][key * KVSTR + c8 + 8], gk + 8);
        cp16(&Vs[buf][key * KVSTR + c8], gv);
        cp16(&Vs[buf][key * KVSTR + c8 + 8], gv + 8);
        if (tid < KB) kmS[buf][tid] = mk[b * S + kt + tid] ? 1.0f : 0.0f;
    };

    load_tiles(0, 0);
    cp_commit();

    for (int kb = 0; kb < S / KB; kb++) {
        const int buf = kb & 1;
        if (kb + 1 < S / KB) {
            load_tiles((kb + 1) * KB, buf ^ 1);
            cp_commit();
            cp_wait<1>();
        } else {
            cp_wait<0>();
        }
        __syncthreads();

        const unsigned sK = buf ? sK1 : sK0;
        const unsigned sV = buf ? sV1 : sV0;

        // --- S = Q @ K^T. sc[j] = key cols 8j..8j+7 ---
        float sc[4][4];
#pragma unroll
        for (int j = 0; j < 4; j++)
#pragma unroll
            for (int r = 0; r < 4; r++) sc[j][r] = 0.0f;
#pragma unroll
        for (int s = 0; s < 4; s++) {
#pragma unroll
            for (int jp = 0; jp < 2; jp++) {
                // non-trans ldsm on K [key][d]: 16 keys x d16
                unsigned addr = sK + 2u * ((jp * 16 + l8 + ln16) * KVSTR + 16 * s + lm);
                unsigned r[4];
                ldsm4(r, addr);
                unsigned bf0[2] = {r[0], r[1]};
                unsigned bf1[2] = {r[2], r[3]};
                mma16(sc[2 * jp], qa[s], bf0);
                mma16(sc[2 * jp + 1], qa[s], bf1);
            }
        }

        // --- P = exp(S/32)*mask; pack to half2 a-frags; accumulate row sums ---
        unsigned pp[4][2];
#pragma unroll
        for (int j = 0; j < 4; j++) {
            const int c0 = 8 * j + 2 * t4;
            float m0 = kmS[buf][c0], m1 = kmS[buf][c0 + 1];
            float p0 = __expf(sc[j][0] * ATT_SCALE) * m0;
            float p1 = __expf(sc[j][1] * ATT_SCALE) * m1;
            float p2 = __expf(sc[j][2] * ATT_SCALE) * m0;
            float p3 = __expf(sc[j][3] * ATT_SCALE) * m1;
            l0 += p0 + p1;
            l1 += p2 + p3;
            pp[j][0] = h2u(__floats2half2_rn(p0, p1));
            pp[j][1] = h2u(__floats2half2_rn(p2, p3));
        }

        // --- O += P @ V : kstep s over keys 16s..16s+15 ---
#pragma unroll
        for (int s = 0; s < 2; s++) {
            unsigned pa[4] = {pp[2 * s][0], pp[2 * s][1], pp[2 * s + 1][0], pp[2 * s + 1][1]};
#pragma unroll
            for (int np = 0; np < 4; np++) {
                // trans ldsm on V [key][d]: k16 x n16 (d cols 16*np..16*np+15)
                unsigned addr = sV + 2u * ((16 * s + l16) * KVSTR + np * 16 + lhi);
                unsigned r[4];
                ldsm4t(r, addr);
                unsigned bf0[2] = {r[0], r[1]};
                unsigned bf1[2] = {r[2], r[3]};
                mma16(oacc[2 * np], pa, bf0);
                mma16(oacc[2 * np + 1], pa, bf1);
            }
        }
        __syncthreads();
    }

    l0 += __shfl_xor_sync(0xffffffffu, l0, 1);
    l0 += __shfl_xor_sync(0xffffffffu, l0, 2);
    l1 += __shfl_xor_sync(0xffffffffu, l1, 1);
    l1 += __shfl_xor_sync(0xffffffffu, l1, 2);

    const int row0 = b * S + q0 + w * 16 + g;
    const float inv0 = mq[row0] ? 1.0f / l0 : 0.0f;
    const float inv1 = mq[row0 + 8] ? 1.0f / l1 : 0.0f;
    __half* o0 = out + (size_t)row0 * E + h * D;
    __half* o1 = o0 + (size_t)8 * E;
#pragma unroll
    for (int n = 0; n < 8; n++) {
        const int c0 = 8 * n + 2 * t4;
        *(__half2*)(o0 + c0) = __floats2half2_rn(oacc[n][0] * inv0, oacc[n][1] * inv0);
        *(__half2*)(o1 + c0) = __floats2half2_rn(oacc[n][2] * inv1, oacc[n][3] * inv1);
    }
}

// ------------------------- layernorm + mask + residual -----------------------
// MODE 0: out = (mask ? LN(x)*g+b : 0) + res   (OutT=half, feeds W1 GEMM)
// MODE 1: out = (mask ? LN(x + res)*g+b : 0)   (OutT=float, final output)
template<int MODE, typename OutT>
__global__ __launch_bounds__(256)
void ln_kernel(const float* __restrict__ x, const float* __restrict__ res,
               const float* __restrict__ g, const float* __restrict__ bb,
               const int* __restrict__ mask, OutT* __restrict__ out) {
    __shared__ float s1[256], s2[256];
    const int row = blockIdx.x;
    const int tid = threadIdx.x;
    const float* xr = x + (size_t)row * E;
    const float* rr = res + (size_t)row * E;
    float v[4];
    float s = 0.0f, sq = 0.0f;
#pragma unroll
    for (int i = 0; i < 4; i++) {
        int c = tid + i * 256;
        float t = xr[c];
        if (MODE == 1) t += rr[c];
        v[i] = t; s += t; sq += t * t;
    }
    s1[tid] = s; s2[tid] = sq;
    __syncthreads();
    for (int off = 128; off > 0; off >>= 1) {
        if (tid < off) { s1[tid] += s1[tid + off]; s2[tid] += s2[tid + off]; }
        __syncthreads();
    }
    float mu = s1[0] * (1.0f / E);
    float var = s2[0] * (1.0f / E) - mu * mu;
    float rstd = rsqrtf(var + 1e-5f);
    float mkf = mask[row] ? 1.0f : 0.0f;
#pragma unroll
    for (int i = 0; i < 4; i++) {
        int c = tid + i * 256;
        float y = (v[i] - mu) * rstd * g[c] + bb[c];
        float o = (MODE == 0) ? (y * mkf + rr[c]) : (y * mkf);
        if (sizeof(OutT) == 2) ((__half*)out)[(size_t)row * E + c] = __float2half(o);
        else                   ((float*)out)[(size_t)row * E + c] = o;
    }
}

// ------------------------- launch -------------------------------------------
extern "C" void kernel_launch(void* const* d_in, const int* in_sizes, int n_in,
                              void* d_out, int out_size) {
    const float* value = (const float*)d_in[0];
    const float* key   = (const float*)d_in[1];
    const float* query = (const float*)d_in[2];
    const void*  mask_k_raw = d_in[3];
    const void*  mask_q_raw = d_in[4];
    const float* Wv = (const float*)d_in[5];
    const float* Wk = (const float*)d_in[6];
    const float* Wq = (const float*)d_in[7];
    const float* Wo = (const float*)d_in[8];
    const float* ln0_g = (const float*)d_in[9];
    const float* ln0_b = (const float*)d_in[10];
    const float* W1 = (const float*)d_in[11];
    const float* b1 = (const float*)d_in[12];
    const float* W2 = (const float*)d_in[13];
    const float* b2 = (const float*)d_in[14];
    const float* ln1_g = (const float*)d_in[15];
    const float* ln1_b = (const float*)d_in[16];
    float* out = (float*)d_out;

    __half *qh, *kh, *vh, *Wqh, *Wkh, *Wvh, *Woh, *W1h, *W2h;
    __half *qph, *kph, *vph, *attnh, *hh, *g1h;
    float *att, *ff;
    int *mq, *mk;
    cudaGetSymbolAddress((void**)&qh,   g_qh);
    cudaGetSymbolAddress((void**)&kh,   g_kh);
    cudaGetSymbolAddress((void**)&vh,   g_vh);
    cudaGetSymbolAddress((void**)&Wqh,  g_Wqh);
    cudaGetSymbolAddress((void**)&Wkh,  g_Wkh);
    cudaGetSymbolAddress((void**)&Wvh,  g_Wvh);
    cudaGetSymbolAddress((void**)&Woh,  g_Woh);
    cudaGetSymbolAddress((void**)&W1h,  g_W1h);
    cudaGetSymbolAddress((void**)&W2h,  g_W2h);
    cudaGetSymbolAddress((void**)&qph,  g_qph);
    cudaGetSymbolAddress((void**)&kph,  g_kph);
    cudaGetSymbolAddress((void**)&vph,  g_vph);
    cudaGetSymbolAddress((void**)&attnh,g_attnh);
    cudaGetSymbolAddress((void**)&hh,   g_hh);
    cudaGetSymbolAddress((void**)&g1h,  g_g1h);
    cudaGetSymbolAddress((void**)&att,  g_att);
    cudaGetSymbolAddress((void**)&ff,   g_ff);
    cudaGetSymbolAddress((void**)&mq,   g_mq);
    cudaGetSymbolAddress((void**)&mk,   g_mk);

    cudaFuncSetAttribute(tc_gemm<0, __half>, cudaFuncAttributeMaxDynamicSharedMemorySize, GEMM_SMEM_BYTES);
    cudaFuncSetAttribute(tc_gemm<0, float>,  cudaFuncAttributeMaxDynamicSharedMemorySize, GEMM_SMEM_BYTES);
    cudaFuncSetAttribute(tc_gemm<1, float>,  cudaFuncAttributeMaxDynamicSharedMemorySize, GEMM_SMEM_BYTES);
    cudaFuncSetAttribute(tc_gemm<2, __half>, cudaFuncAttributeMaxDynamicSharedMemorySize, GEMM_SMEM_BYTES);

    mask_convert_kernel<<<1, 256>>>(mask_k_raw, mk, NROWS);
    mask_convert_kernel<<<1, 256>>>(mask_q_raw, mq, NROWS);

    // fp32 -> fp16 conversions (inputs + weights)
    f2h_kernel<<<512, 256>>>(query, qh, NROWS * E / 4);
    f2h_kernel<<<512, 256>>>(key,   kh, NROWS * E / 4);
    f2h_kernel<<<512, 256>>>(value, vh, NROWS * E / 4);
    f2h_kernel<<<256, 256>>>(Wq, Wqh, E * E / 4);
    f2h_kernel<<<256, 256>>>(Wk, Wkh, E * E / 4);
    f2h_kernel<<<256, 256>>>(Wv, Wvh, E * E / 4);
    f2h_kernel<<<256, 256>>>(Wo, Woh, E * E / 4);
    f2h_kernel<<<512, 256>>>(W1, W1h, E * FFDIM / 4);
    f2h_kernel<<<512, 256>>>(W2, W2h, FFDIM * E / 4);

    dim3 gE(E / 128, NROWS / 128);        // 8 x 32
    dim3 gF(FFDIM / 128, NROWS / 128);    // 16 x 32

    tc_gemm<0, __half><<<gE, 256, GEMM_SMEM_BYTES>>>(qh, Wqh, nullptr, qph, NROWS, E, E);
    tc_gemm<0, __half><<<gE, 256, GEMM_SMEM_BYTES>>>(kh, Wkh, nullptr, kph, NROWS, E, E);
    tc_gemm<0, __half><<<gE, 256, GEMM_SMEM_BYTES>>>(vh, Wvh, nullptr, vph, NROWS, E, E);

    attn_tc_kernel<<<dim3(S / 64, H, B), 128>>>(qph, kph, vph, mq, mk, attnh);

    tc_gemm<0, float><<<gE, 256, GEMM_SMEM_BYTES>>>(attnh, Woh, nullptr, att, NROWS, E, E);

    ln_kernel<0, __half><<<NROWS, 256>>>(att, query, ln0_g, ln0_b, mq, hh);

    tc_gemm<2, __half><<<gF, 256, GEMM_SMEM_BYTES>>>(hh, W1h, b1, g1h, NROWS, FFDIM, E);
    tc_gemm<1, float><<<gE, 256, GEMM_SMEM_BYTES>>>(g1h, W2h, b2, ff, NROWS, E, FFDIM);

    ln_kernel<1, float><<<NROWS, 256>>>(ff, query, ln1_g, ln1_b, mq, out);
}

// round 9
// speedup vs baseline: 2.1503x; 1.0780x over previous
#include <cuda_runtime.h>
#include <cuda_fp16.h>
#include <math.h>

#define E 1024
#define H 16
#define D 64
#define B 4
#define S 1024
#define NROWS (B*S)     // 4096
#define FFDIM 2048
#define ATT_SCALE 0.03125f    // 1/sqrt(1024)

// ------------------------- scratch (no allocations allowed) -----------------
__device__ __half g_qh[NROWS * E];      // fp16 copies of inputs
__device__ __half g_kh[NROWS * E];
__device__ __half g_vh[NROWS * E];
__device__ __half g_Wqh[E * E];
__device__ __half g_Wkh[E * E];
__device__ __half g_Wvh[E * E];
__device__ __half g_Woh[E * E];
__device__ __half g_W1h[E * FFDIM];
__device__ __half g_W2h[FFDIM * E];
__device__ __half g_qph[NROWS * E];     // projections (fp16)
__device__ __half g_kph[NROWS * E];
__device__ __half g_vph[NROWS * E];
__device__ __half g_attnh[NROWS * E];   // attention output (fp16)
__device__ float  g_att[NROWS * E];     // Wo output (fp32, -> LN)
__device__ __half g_hh[NROWS * E];      // LN0 + residual (fp16, -> W1)
__device__ __half g_g1h[NROWS * FFDIM]; // gelu(W1) (fp16, -> W2)
__device__ float  g_ff[NROWS * E];      // W2 output (fp32, -> LN)
__device__ int    g_mq[NROWS];
__device__ int    g_mk[NROWS];

// ------------------------- mask canonicalization (both masks, one launch) ---
__device__ __forceinline__ void mask_conv_one(const void* raw, int* out, int n,
                                              int tid, int nthr, int* s_flags) {
    const unsigned char* p = (const unsigned char*)raw;
    int big = 0, nonal = 0;
    for (int i = tid; i < n; i += nthr) {
        unsigned char v = p[i];
        if (v > 1) big = 1;
        if ((i & 3) != 0 && v != 0) nonal = 1;
    }
    if (big)   atomicOr(&s_flags[0], 1);
    if (nonal) atomicOr(&s_flags[1], 1);
    __syncthreads();
    int kind = s_flags[0] ? 2 : (s_flags[1] ? 1 : 0);
    for (int i = tid; i < n; i += nthr) {
        int v;
        if (kind == 2)      v = (((const float*)raw)[i] != 0.0f);
        else if (kind == 1) v = (p[i] != 0);
        else                v = (((const int*)raw)[i] != 0);
        out[i] = v;
    }
}

__global__ void mask_convert2_kernel(const void* __restrict__ rawk, int* __restrict__ outk,
                                     const void* __restrict__ rawq, int* __restrict__ outq,
                                     int n) {
    __shared__ int fk[2], fq[2];
    if (threadIdx.x == 0) { fk[0] = fk[1] = fq[0] = fq[1] = 0; }
    __syncthreads();
    mask_conv_one(rawk, outk, n, threadIdx.x, blockDim.x, fk);
    __syncthreads();
    mask_conv_one(rawq, outq, n, threadIdx.x, blockDim.x, fq);
}

// ------------------------- fused fp32 -> fp16 conversion ---------------------
// Segment sizes are compile-time: 3 x NE, 4 x EE, 2 x EF (in float4 quads).
#define Q_NE (NROWS * E / 4)     // 1048576
#define Q_EE (E * E / 4)         // 262144
#define Q_EF (E * FFDIM / 4)     // 524288
#define Q_TOT (3*Q_NE + 4*Q_EE + 2*Q_EF)

__global__ __launch_bounds__(256)
void f2h_all_kernel(const float* s0, __half* d0, const float* s1, __half* d1,
                    const float* s2, __half* d2, const float* s3, __half* d3,
                    const float* s4, __half* d4, const float* s5, __half* d5,
                    const float* s6, __half* d6, const float* s7, __half* d7,
                    const float* s8, __half* d8) {
    int i = blockIdx.x * blockDim.x + threadIdx.x;
    const int stride = gridDim.x * blockDim.x;
    for (; i < Q_TOT; i += stride) {
        const float* src; __half* dst; int off;
        int t = i;
        if (t < 3 * Q_NE) {
            int seg = t / Q_NE; off = t - seg * Q_NE;
            src = seg == 0 ? s0 : (seg == 1 ? s1 : s2);
            dst = seg == 0 ? d0 : (seg == 1 ? d1 : d2);
        } else if (t < 3 * Q_NE + 4 * Q_EE) {
            t -= 3 * Q_NE;
            int seg = t / Q_EE; off = t - seg * Q_EE;
            src = seg == 0 ? s3 : (seg == 1 ? s4 : (seg == 2 ? s5 : s6));
            dst = seg == 0 ? d3 : (seg == 1 ? d4 : (seg == 2 ? d5 : d6));
        } else {
            t -= 3 * Q_NE + 4 * Q_EE;
            int seg = t / Q_EF; off = t - seg * Q_EF;
            src = seg == 0 ? s7 : s8;
            dst = seg == 0 ? d7 : d8;
        }
        float4 v = ((const float4*)src)[off];
        __half2* o = (__half2*)dst + 2 * off;
        o[0] = __floats2half2_rn(v.x, v.y);
        o[1] = __floats2half2_rn(v.z, v.w);
    }
}

// ------------------------- mma / ldmatrix helpers ----------------------------
__device__ __forceinline__ unsigned h2u(__half2 h) {
    union { __half2 h; unsigned u; } cvt;
    cvt.h = h;
    return cvt.u;
}

__device__ __forceinline__ void mma16(float c[4], const unsigned a[4], const unsigned b[2]) {
    asm volatile(
        "mma.sync.aligned.m16n8k16.row.col.f32.f16.f16.f32 "
        "{%0,%1,%2,%3}, {%4,%5,%6,%7}, {%8,%9}, {%0,%1,%2,%3};"
        : "+f"(c[0]), "+f"(c[1]), "+f"(c[2]), "+f"(c[3])
        : "r"(a[0]), "r"(a[1]), "r"(a[2]), "r"(a[3]), "r"(b[0]), "r"(b[1]));
}

__device__ __forceinline__ void ldsm4(unsigned r[4], unsigned saddr) {
    asm volatile("ldmatrix.sync.aligned.m8n8.x4.shared.b16 {%0,%1,%2,%3}, [%4];"
                 : "=r"(r[0]), "=r"(r[1]), "=r"(r[2]), "=r"(r[3]) : "r"(saddr));
}
__device__ __forceinline__ void ldsm4t(unsigned r[4], unsigned saddr) {
    asm volatile("ldmatrix.sync.aligned.m8n8.x4.trans.shared.b16 {%0,%1,%2,%3}, [%4];"
                 : "=r"(r[0]), "=r"(r[1]), "=r"(r[2]), "=r"(r[3]) : "r"(saddr));
}

__device__ __forceinline__ void cp16(void* smem, const void* g) {
    unsigned s = (unsigned)__cvta_generic_to_shared(smem);
    asm volatile("cp.async.cg.shared.global [%0], [%1], 16;\n" :: "r"(s), "l"(g));
}
__device__ __forceinline__ void cp_commit() { asm volatile("cp.async.commit_group;\n"); }
template<int N> __device__ __forceinline__ void cp_wait() {
    asm volatile("cp.async.wait_group %0;\n" :: "n"(N));
}

// ------------------------- fp16 tensor-core GEMM -----------------------------
// (unchanged from round 8: 128x128 tile, BK=32, 8 warps, m16n8k16,
//  4-stage cp.async circular pipeline, one __syncthreads per iter)
#define ASTR 40
#define BSTR 136
#define GSTAGES 4
#define STAGE_H (128 * ASTR + 32 * BSTR)           // 9472 halfs per stage
#define GEMM_SMEM_BYTES (GSTAGES * STAGE_H * 2)    // 75776 B

template<int EPI, typename OutT>
__global__ __launch_bounds__(256, 2)
void tc_gemm(const __half* __restrict__ A, const __half* __restrict__ Bm,
             const float* __restrict__ bias, OutT* __restrict__ C,
             int M, int N, int K) {
    extern __shared__ __half smem[];
    const int tid = threadIdx.x;
    const int bm = blockIdx.y * 128, bn = blockIdx.x * 128;
    const int warp = tid >> 5, lane = tid & 31;
    const int wm = (warp & 1) * 64;
    const int wn = (warp >> 1) * 32;
    const int g = lane >> 2, t4 = lane & 3;
    const int l16 = lane & 15, lhi = (lane & 16) ? 8 : 0;

    const int am = tid >> 1, ac = (tid & 1) * 16;
    const int br = tid >> 3, bc = (tid & 7) * 16;
    const __half* Aptr = A + (size_t)(bm + am) * K + ac;
    const __half* Bptr = Bm + (size_t)br * N + bn + bc;

    const unsigned sbase = (unsigned)__cvta_generic_to_shared(smem);

    float c[4][4][4];
#pragma unroll
    for (int i = 0; i < 4; i++)
#pragma unroll
        for (int j = 0; j < 4; j++)
#pragma unroll
            for (int r = 0; r < 4; r++) c[i][j][r] = 0.0f;

    auto load_stage = [&](int buf, int tI) {
        __half* As = smem + buf * STAGE_H;
        __half* Bs = As + 128 * ASTR;
        const __half* Ap = Aptr + tI * 32;
        const __half* Bp = Bptr + (size_t)tI * 32 * N;
        cp16(&As[am * ASTR + ac], Ap);
        cp16(&As[am * ASTR + ac + 8], Ap + 8);
        cp16(&Bs[br * BSTR + bc], Bp);
        cp16(&Bs[br * BSTR + bc + 8], Bp + 8);
    };

    const int T = K / 32;
#pragma unroll
    for (int s = 0; s < GSTAGES - 1; s++) {
        load_stage(s, s);
        cp_commit();
    }

    for (int tI = 0; tI < T; tI++) {
        const int buf = tI & (GSTAGES - 1);
        cp_wait<GSTAGES - 2>();
        __syncthreads();
        if (tI + GSTAGES - 1 < T)
            load_stage((tI + GSTAGES - 1) & (GSTAGES - 1), tI + GSTAGES - 1);
        cp_commit();

        const unsigned sA = sbase + 2u * (buf * STAGE_H);
        const unsigned sB = sA + 2u * (128 * ASTR);
#pragma unroll
        for (int step = 0; step < 2; step++) {
            const int k0 = step * 16;
            unsigned af[4][4], bf[4][2];
#pragma unroll
            for (int i = 0; i < 4; i++) {
                unsigned addr = sA + 2u * ((wm + i * 16 + l16) * ASTR + k0 + lhi);
                ldsm4(af[i], addr);
            }
#pragma unroll
            for (int jp = 0; jp < 2; jp++) {
                unsigned addr = sB + 2u * ((k0 + l16) * BSTR + wn + jp * 16 + lhi);
                unsigned r[4];
                ldsm4t(r, addr);
                bf[2 * jp][0] = r[0];     bf[2 * jp][1] = r[1];
                bf[2 * jp + 1][0] = r[2]; bf[2 * jp + 1][1] = r[3];
            }
#pragma unroll
            for (int i = 0; i < 4; i++)
#pragma unroll
                for (int j = 0; j < 4; j++)
                    mma16(c[i][j], af[i], bf[j]);
        }
    }

#pragma unroll
    for (int i = 0; i < 4; i++) {
#pragma unroll
        for (int j = 0; j < 4; j++) {
            const int row0 = bm + wm + i * 16 + g;
            const int col = bn + wn + j * 8 + 2 * t4;
            float v0 = c[i][j][0], v1 = c[i][j][1], v2 = c[i][j][2], v3 = c[i][j][3];
            if (EPI >= 1) {
                float b0 = bias[col], b1 = bias[col + 1];
                v0 += b0; v1 += b1; v2 += b0; v3 += b1;
            }
            if (EPI == 2) {
                v0 *= 1.0f / (1.0f + __expf(-1.702f * v0));
                v1 *= 1.0f / (1.0f + __expf(-1.702f * v1));
                v2 *= 1.0f / (1.0f + __expf(-1.702f * v2));
                v3 *= 1.0f / (1.0f + __expf(-1.702f * v3));
            }
            if (sizeof(OutT) == 2) {
                *(__half2*)((__half*)C + (size_t)row0 * N + col) = __floats2half2_rn(v0, v1);
                *(__half2*)((__half*)C + (size_t)(row0 + 8) * N + col) = __floats2half2_rn(v2, v3);
            } else {
                float2 p0 = {v0, v1}, p1 = {v2, v3};
                *(float2*)((float*)C + (size_t)row0 * N + col) = p0;
                *(float2*)((float*)C + (size_t)(row0 + 8) * N + col) = p1;
            }
        }
    }
}

// ------------------------- fp16 tensor-core flash attention ------------------
// Block: 128 q x (b,h). 4 warps, each owns 32 q rows (two m16 tiles).
// K/V ldsm fragments shared across both m-tiles -> mma:ldsm doubled vs r8.
#define KVSTR 72
#define KB 32

__global__ __launch_bounds__(128)
void attn_tc_kernel(const __half* __restrict__ qp, const __half* __restrict__ kp,
                    const __half* __restrict__ vp, const int* __restrict__ mq,
                    const int* __restrict__ mk, __half* __restrict__ out) {
    __shared__ __half Ks[2][KB * KVSTR];
    __shared__ __half Vs[2][KB * KVSTR];
    __shared__ float kmS[2][KB];

    const int b = blockIdx.z, h = blockIdx.y;
    const int q0 = blockIdx.x * 128;
    const int tid = threadIdx.x;
    const int w = tid >> 5, lane = tid & 31;
    const int g = lane >> 2, t4 = lane & 3;
    const int l16 = lane & 15, lhi = (lane & 16) ? 8 : 0;
    const int l8 = lane & 7, lm = ((lane & 8) ? 8 : 0), ln16 = (lane & 16) ? 8 : 0;

    const unsigned sK0 = (unsigned)__cvta_generic_to_shared(&Ks[0][0]);
    const unsigned sK1 = (unsigned)__cvta_generic_to_shared(&Ks[1][0]);
    const unsigned sV0 = (unsigned)__cvta_generic_to_shared(&Vs[0][0]);
    const unsigned sV1 = (unsigned)__cvta_generic_to_shared(&Vs[1][0]);

    // Q fragments (persistent): i-th m16 tile rows q0+32w+16i+g (+8)
    unsigned qa[2][4][4];
#pragma unroll
    for (int i = 0; i < 2; i++) {
        const __half* Qr0 = qp + (size_t)(b * S + q0 + w * 32 + i * 16 + g) * E + h * D;
        const __half* Qr1 = Qr0 + (size_t)8 * E;
#pragma unroll
        for (int s = 0; s < 4; s++) {
            qa[i][s][0] = *(const unsigned*)&Qr0[16 * s + 2 * t4];
            qa[i][s][1] = *(const unsigned*)&Qr1[16 * s + 2 * t4];
            qa[i][s][2] = *(const unsigned*)&Qr0[16 * s + 8 + 2 * t4];
            qa[i][s][3] = *(const unsigned*)&Qr1[16 * s + 8 + 2 * t4];
        }
    }

    float oacc[2][8][4];
#pragma unroll
    for (int i = 0; i < 2; i++)
#pragma unroll
        for (int n = 0; n < 8; n++)
#pragma unroll
            for (int r = 0; r < 4; r++) oacc[i][n][r] = 0.0f;
    float lsum[2][2] = {{0.0f, 0.0f}, {0.0f, 0.0f}};

    auto load_tiles = [&](int kt, int buf) {
        int key = tid >> 2, c8 = (tid & 3) * 16;
        const __half* gk = kp + (size_t)(b * S + kt + key) * E + h * D + c8;
        const __half* gv = vp + (size_t)(b * S + kt + key) * E + h * D + c8;
        cp16(&Ks[buf][key * KVSTR + c8], gk);
        cp16(&Ks[buf][key * KVSTR + c8 + 8], gk + 8);
        cp16(&Vs[buf][key * KVSTR + c8], gv);
        cp16(&Vs[buf][key * KVSTR + c8 + 8], gv + 8);
        if (tid < KB) kmS[buf][tid] = mk[b * S + kt + tid] ? 1.0f : 0.0f;
    };

    load_tiles(0, 0);
    cp_commit();

    for (int kb = 0; kb < S / KB; kb++) {
        const int buf = kb & 1;
        if (kb + 1 < S / KB) {
            load_tiles((kb + 1) * KB, buf ^ 1);
            cp_commit();
            cp_wait<1>();
        } else {
            cp_wait<0>();
        }
        __syncthreads();

        const unsigned sK = buf ? sK1 : sK0;
        const unsigned sV = buf ? sV1 : sV0;

        // --- S = Q @ K^T : sc[i][j] = m-tile i, key cols 8j..8j+7 ---
        float sc[2][4][4];
#pragma unroll
        for (int i = 0; i < 2; i++)
#pragma unroll
            for (int j = 0; j < 4; j++)
#pragma unroll
                for (int r = 0; r < 4; r++) sc[i][j][r] = 0.0f;
#pragma unroll
        for (int s = 0; s < 4; s++) {
#pragma unroll
            for (int jp = 0; jp < 2; jp++) {
                unsigned addr = sK + 2u * ((jp * 16 + l8 + ln16) * KVSTR + 16 * s + lm);
                unsigned r[4];
                ldsm4(r, addr);
                unsigned bf0[2] = {r[0], r[1]};
                unsigned bf1[2] = {r[2], r[3]};
#pragma unroll
                for (int i = 0; i < 2; i++) {
                    mma16(sc[i][2 * jp], qa[i][s], bf0);
                    mma16(sc[i][2 * jp + 1], qa[i][s], bf1);
                }
            }
        }

        // --- P = exp(S/32)*mask; pack; row sums ---
        unsigned pp[2][4][2];
#pragma unroll
        for (int i = 0; i < 2; i++) {
#pragma unroll
            for (int j = 0; j < 4; j++) {
                const int c0 = 8 * j + 2 * t4;
                float m0 = kmS[buf][c0], m1 = kmS[buf][c0 + 1];
                float p0 = __expf(sc[i][j][0] * ATT_SCALE) * m0;
                float p1 = __expf(sc[i][j][1] * ATT_SCALE) * m1;
                float p2 = __expf(sc[i][j][2] * ATT_SCALE) * m0;
                float p3 = __expf(sc[i][j][3] * ATT_SCALE) * m1;
                lsum[i][0] += p0 + p1;
                lsum[i][1] += p2 + p3;
                pp[i][j][0] = h2u(__floats2half2_rn(p0, p1));
                pp[i][j][1] = h2u(__floats2half2_rn(p2, p3));
            }
        }

        // --- O += P @ V ---
#pragma unroll
        for (int s = 0; s < 2; s++) {
            unsigned pa[2][4];
#pragma unroll
            for (int i = 0; i < 2; i++) {
                pa[i][0] = pp[i][2 * s][0]; pa[i][1] = pp[i][2 * s][1];
                pa[i][2] = pp[i][2 * s + 1][0]; pa[i][3] = pp[i][2 * s + 1][1];
            }
#pragma unroll
            for (int np = 0; np < 4; np++) {
                unsigned addr = sV + 2u * ((16 * s + l16) * KVSTR + np * 16 + lhi);
                unsigned r[4];
                ldsm4t(r, addr);
                unsigned bf0[2] = {r[0], r[1]};
                unsigned bf1[2] = {r[2], r[3]};
#pragma unroll
                for (int i = 0; i < 2; i++) {
                    mma16(oacc[i][2 * np], pa[i], bf0);
                    mma16(oacc[i][2 * np + 1], pa[i], bf1);
                }
            }
        }
        __syncthreads();
    }

#pragma unroll
    for (int i = 0; i < 2; i++) {
        float l0 = lsum[i][0], l1 = lsum[i][1];
        l0 += __shfl_xor_sync(0xffffffffu, l0, 1);
        l0 += __shfl_xor_sync(0xffffffffu, l0, 2);
        l1 += __shfl_xor_sync(0xffffffffu, l1, 1);
        l1 += __shfl_xor_sync(0xffffffffu, l1, 2);

        const int row0 = b * S + q0 + w * 32 + i * 16 + g;
        const float inv0 = mq[row0] ? 1.0f / l0 : 0.0f;
        const float inv1 = mq[row0 + 8] ? 1.0f / l1 : 0.0f;
        __half* o0 = out + (size_t)row0 * E + h * D;
        __half* o1 = o0 + (size_t)8 * E;
#pragma unroll
        for (int n = 0; n < 8; n++) {
            const int c0 = 8 * n + 2 * t4;
            *(__half2*)(o0 + c0) = __floats2half2_rn(oacc[i][n][0] * inv0, oacc[i][n][1] * inv0);
            *(__half2*)(o1 + c0) = __floats2half2_rn(oacc[i][n][2] * inv1, oacc[i][n][3] * inv1);
        }
    }
}

// ------------------------- layernorm + mask + residual -----------------------
template<int MODE, typename OutT>
__global__ __launch_bounds__(256)
void ln_kernel(const float* __restrict__ x, const float* __restrict__ res,
               const float* __restrict__ g, const float* __restrict__ bb,
               const int* __restrict__ mask, OutT* __restrict__ out) {
    __shared__ float s1[256], s2[256];
    const int row = blockIdx.x;
    const int tid = threadIdx.x;
    const float* xr = x + (size_t)row * E;
    const float* rr = res + (size_t)row * E;
    float v[4];
    float s = 0.0f, sq = 0.0f;
#pragma unroll
    for (int i = 0; i < 4; i++) {
        int c = tid + i * 256;
        float t = xr[c];
        if (MODE == 1) t += rr[c];
        v[i] = t; s += t; sq += t * t;
    }
    s1[tid] = s; s2[tid] = sq;
    __syncthreads();
    for (int off = 128; off > 0; off >>= 1) {
        if (tid < off) { s1[tid] += s1[tid + off]; s2[tid] += s2[tid + off]; }
        __syncthreads();
    }
    float mu = s1[0] * (1.0f / E);
    float var = s2[0] * (1.0f / E) - mu * mu;
    float rstd = rsqrtf(var + 1e-5f);
    float mkf = mask[row] ? 1.0f : 0.0f;
#pragma unroll
    for (int i = 0; i < 4; i++) {
        int c = tid + i * 256;
        float y = (v[i] - mu) * rstd * g[c] + bb[c];
        float o = (MODE == 0) ? (y * mkf + rr[c]) : (y * mkf);
        if (sizeof(OutT) == 2) ((__half*)out)[(size_t)row * E + c] = __float2half(o);
        else                   ((float*)out)[(size_t)row * E + c] = o;
    }
}

// ------------------------- launch -------------------------------------------
extern "C" void kernel_launch(void* const* d_in, const int* in_sizes, int n_in,
                              void* d_out, int out_size) {
    const float* value = (const float*)d_in[0];
    const float* key   = (const float*)d_in[1];
    const float* query = (const float*)d_in[2];
    const void*  mask_k_raw = d_in[3];
    const void*  mask_q_raw = d_in[4];
    const float* Wv = (const float*)d_in[5];
    const float* Wk = (const float*)d_in[6];
    const float* Wq = (const float*)d_in[7];
    const float* Wo = (const float*)d_in[8];
    const float* ln0_g = (const float*)d_in[9];
    const float* ln0_b = (const float*)d_in[10];
    const float* W1 = (const float*)d_in[11];
    const float* b1 = (const float*)d_in[12];
    const float* W2 = (const float*)d_in[13];
    const float* b2 = (const float*)d_in[14];
    const float* ln1_g = (const float*)d_in[15];
    const float* ln1_b = (const float*)d_in[16];
    float* out = (float*)d_out;

    __half *qh, *kh, *vh, *Wqh, *Wkh, *Wvh, *Woh, *W1h, *W2h;
    __half *qph, *kph, *vph, *attnh, *hh, *g1h;
    float *att, *ff;
    int *mq, *mk;
    cudaGetSymbolAddress((void**)&qh,   g_qh);
    cudaGetSymbolAddress((void**)&kh,   g_kh);
    cudaGetSymbolAddress((void**)&vh,   g_vh);
    cudaGetSymbolAddress((void**)&Wqh,  g_Wqh);
    cudaGetSymbolAddress((void**)&Wkh,  g_Wkh);
    cudaGetSymbolAddress((void**)&Wvh,  g_Wvh);
    cudaGetSymbolAddress((void**)&Woh,  g_Woh);
    cudaGetSymbolAddress((void**)&W1h,  g_W1h);
    cudaGetSymbolAddress((void**)&W2h,  g_W2h);
    cudaGetSymbolAddress((void**)&qph,  g_qph);
    cudaGetSymbolAddress((void**)&kph,  g_kph);
    cudaGetSymbolAddress((void**)&vph,  g_vph);
    cudaGetSymbolAddress((void**)&attnh,g_attnh);
    cudaGetSymbolAddress((void**)&hh,   g_hh);
    cudaGetSymbolAddress((void**)&g1h,  g_g1h);
    cudaGetSymbolAddress((void**)&att,  g_att);
    cudaGetSymbolAddress((void**)&ff,   g_ff);
    cudaGetSymbolAddress((void**)&mq,   g_mq);
    cudaGetSymbolAddress((void**)&mk,   g_mk);

    cudaFuncSetAttribute(tc_gemm<0, __half>, cudaFuncAttributeMaxDynamicSharedMemorySize, GEMM_SMEM_BYTES);
    cudaFuncSetAttribute(tc_gemm<0, float>,  cudaFuncAttributeMaxDynamicSharedMemorySize, GEMM_SMEM_BYTES);
    cudaFuncSetAttribute(tc_gemm<1, float>,  cudaFuncAttributeMaxDynamicSharedMemorySize, GEMM_SMEM_BYTES);
    cudaFuncSetAttribute(tc_gemm<2, __half>, cudaFuncAttributeMaxDynamicSharedMemorySize, GEMM_SMEM_BYTES);

    mask_convert2_kernel<<<1, 256>>>(mask_k_raw, mk, mask_q_raw, mq, NROWS);

    // single fused fp32 -> fp16 conversion (inputs + all weights)
    f2h_all_kernel<<<1184, 256>>>(query, qh, key, kh, value, vh,
                                  Wq, Wqh, Wk, Wkh, Wv, Wvh, Wo, Woh,
                                  W1, W1h, W2, W2h);

    dim3 gE(E / 128, NROWS / 128);        // 8 x 32
    dim3 gF(FFDIM / 128, NROWS / 128);    // 16 x 32

    tc_gemm<0, __half><<<gE, 256, GEMM_SMEM_BYTES>>>(qh, Wqh, nullptr, qph, NROWS, E, E);
    tc_gemm<0, __half><<<gE, 256, GEMM_SMEM_BYTES>>>(kh, Wkh, nullptr, kph, NROWS, E, E);
    tc_gemm<0, __half><<<gE, 256, GEMM_SMEM_BYTES>>>(vh, Wvh, nullptr, vph, NROWS, E, E);

    attn_tc_kernel<<<dim3(S / 128, H, B), 128>>>(qph, kph, vph, mq, mk, attnh);

    tc_gemm<0, float><<<gE, 256, GEMM_SMEM_BYTES>>>(attnh, Woh, nullptr, att, NROWS, E, E);

    ln_kernel<0, __half><<<NROWS, 256>>>(att, query, ln0_g, ln0_b, mq, hh);

    tc_gemm<2, __half><<<gF, 256, GEMM_SMEM_BYTES>>>(hh, W1h, b1, g1h, NROWS, FFDIM, E);
    tc_gemm<1, float><<<gE, 256, GEMM_SMEM_BYTES>>>(g1h, W2h, b2, ff, NROWS, E, FFDIM);

    ln_kernel<1, float><<<NROWS, 256>>>(ff, query, ln1_g, ln1_b, mq, out);
}

// round 11
// speedup vs baseline: 2.3974x; 1.1149x over previous
#include <cuda_runtime.h>
#include <cuda_fp16.h>
#include <math.h>

#define E 1024
#define H 16
#define D 64
#define B 4
#define S 1024
#define NROWS (B*S)     // 4096
#define FFDIM 2048
#define ATT_SCALE 0.03125f    // 1/sqrt(1024)

// ------------------------- scratch (no allocations allowed) -----------------
__device__ __half g_qh[NROWS * E];
__device__ __half g_kh[NROWS * E];
__device__ __half g_vh[NROWS * E];
__device__ __half g_Wqh[E * E];
__device__ __half g_Wkh[E * E];
__device__ __half g_Wvh[E * E];
__device__ __half g_Woh[E * E];
__device__ __half g_W1h[E * FFDIM];
__device__ __half g_W2h[FFDIM * E];
__device__ __half g_qph[NROWS * E];
__device__ __half g_kph[NROWS * E];
__device__ __half g_vph[NROWS * E];
__device__ __half g_attnh[NROWS * E];
__device__ float  g_att[NROWS * E];
__device__ __half g_hh[NROWS * E];
__device__ __half g_g1h[NROWS * FFDIM];
__device__ float  g_ff[NROWS * E];
__device__ int    g_mq[NROWS];
__device__ int    g_mk[NROWS];

// ------------------------- mask canonicalization -----------------------------
__device__ __forceinline__ void mask_conv_one(const void* raw, int* out, int n,
                                              int tid, int nthr, int* s_flags) {
    const unsigned char* p = (const unsigned char*)raw;
    int big = 0, nonal = 0;
    for (int i = tid; i < n; i += nthr) {
        unsigned char v = p[i];
        if (v > 1) big = 1;
        if ((i & 3) != 0 && v != 0) nonal = 1;
    }
    if (big)   atomicOr(&s_flags[0], 1);
    if (nonal) atomicOr(&s_flags[1], 1);
    __syncthreads();
    int kind = s_flags[0] ? 2 : (s_flags[1] ? 1 : 0);
    for (int i = tid; i < n; i += nthr) {
        int v;
        if (kind == 2)      v = (((const float*)raw)[i] != 0.0f);
        else if (kind == 1) v = (p[i] != 0);
        else                v = (((const int*)raw)[i] != 0);
        out[i] = v;
    }
}
__global__ void mask_convert2_kernel(const void* __restrict__ rawk, int* __restrict__ outk,
                                     const void* __restrict__ rawq, int* __restrict__ outq,
                                     int n) {
    __shared__ int fk[2], fq[2];
    if (threadIdx.x == 0) { fk[0] = fk[1] = fq[0] = fq[1] = 0; }
    __syncthreads();
    mask_conv_one(rawk, outk, n, threadIdx.x, blockDim.x, fk);
    __syncthreads();
    mask_conv_one(rawq, outq, n, threadIdx.x, blockDim.x, fq);
}

// ------------------------- fused fp32 -> fp16 conversion ---------------------
#define Q_NE (NROWS * E / 4)     // 1048576
#define Q_EE (E * E / 4)         // 262144
#define Q_EF (E * FFDIM / 4)     // 524288
#define Q_TOT (3*Q_NE + 4*Q_EE + 2*Q_EF)

__global__ __launch_bounds__(256)
void f2h_all_kernel(const float* s0, __half* d0, const float* s1, __half* d1,
                    const float* s2, __half* d2, const float* s3, __half* d3,
                    const float* s4, __half* d4, const float* s5, __half* d5,
                    const float* s6, __half* d6, const float* s7, __half* d7,
                    const float* s8, __half* d8) {
    int i = blockIdx.x * blockDim.x + threadIdx.x;
    const int stride = gridDim.x * blockDim.x;
    for (; i < Q_TOT; i += stride) {
        const float* src; __half* dst; int off;
        int t = i;
        if (t < 3 * Q_NE) {
            int seg = t / Q_NE; off = t - seg * Q_NE;
            src = seg == 0 ? s0 : (seg == 1 ? s1 : s2);
            dst = seg == 0 ? d0 : (seg == 1 ? d1 : d2);
        } else if (t < 3 * Q_NE + 4 * Q_EE) {
            t -= 3 * Q_NE;
            int seg = t / Q_EE; off = t - seg * Q_EE;
            src = seg == 0 ? s3 : (seg == 1 ? s4 : (seg == 2 ? s5 : s6));
            dst = seg == 0 ? d3 : (seg == 1 ? d4 : (seg == 2 ? d5 : d6));
        } else {
            t -= 3 * Q_NE + 4 * Q_EE;
            int seg = t / Q_EF; off = t - seg * Q_EF;
            src = seg == 0 ? s7 : s8;
            dst = seg == 0 ? d7 : d8;
        }
        float4 v = ((const float4*)src)[off];
        __half2* o = (__half2*)dst + 2 * off;
        o[0] = __floats2half2_rn(v.x, v.y);
        o[1] = __floats2half2_rn(v.z, v.w);
    }
}

// ------------------------- mma / ldmatrix helpers ----------------------------
__device__ __forceinline__ unsigned h2u(__half2 h) {
    union { __half2 h; unsigned u; } c; c.h = h; return c.u;
}
__device__ __forceinline__ void mma16(float c[4], const unsigned a[4], const unsigned b[2]) {
    asm volatile(
        "mma.sync.aligned.m16n8k16.row.col.f32.f16.f16.f32 "
        "{%0,%1,%2,%3}, {%4,%5,%6,%7}, {%8,%9}, {%0,%1,%2,%3};"
        : "+f"(c[0]), "+f"(c[1]), "+f"(c[2]), "+f"(c[3])
        : "r"(a[0]), "r"(a[1]), "r"(a[2]), "r"(a[3]), "r"(b[0]), "r"(b[1]));
}
__device__ __forceinline__ void ldsm4(unsigned r[4], unsigned saddr) {
    asm volatile("ldmatrix.sync.aligned.m8n8.x4.shared.b16 {%0,%1,%2,%3}, [%4];"
                 : "=r"(r[0]), "=r"(r[1]), "=r"(r[2]), "=r"(r[3]) : "r"(saddr));
}
__device__ __forceinline__ void ldsm4t(unsigned r[4], unsigned saddr) {
    asm volatile("ldmatrix.sync.aligned.m8n8.x4.trans.shared.b16 {%0,%1,%2,%3}, [%4];"
                 : "=r"(r[0]), "=r"(r[1]), "=r"(r[2]), "=r"(r[3]) : "r"(saddr));
}
__device__ __forceinline__ void cp16(void* smem, const void* g) {
    unsigned s = (unsigned)__cvta_generic_to_shared(smem);
    asm volatile("cp.async.cg.shared.global [%0], [%1], 16;\n" :: "r"(s), "l"(g));
}
__device__ __forceinline__ void cp_commit() { asm volatile("cp.async.commit_group;\n"); }
template<int N> __device__ __forceinline__ void cp_wait() {
    asm volatile("cp.async.wait_group %0;\n" :: "n"(N));
}

// ------------------------- fp16 tensor-core GEMM -----------------------------
// C[M,N] = A[M,K] @ Bm[K,N] (+bias fp32) (+quick_gelu). A,Bm fp16 row-major.
// 128x128 tile, BK=32, FOUR warps (2M x 2N), 64x64 per warp, m16n8k16.
// Per k16-step: 8 LDSM feed 32 HMMA (ratio 4:1) -> long independent MMA
// chains to cover LDS latency. 4-stage cp.async circular pipeline.
// A smem [m][k] stride 40 halfs; B smem [k][n] stride 136 halfs (both
// ldmatrix conflict-free). launch_bounds(128,2) -> 2 CTAs/SM.
#define ASTR 40
#define BSTR 136
#define GSTAGES 4
#define STAGE_H (128 * ASTR + 32 * BSTR)           // 9472 halfs per stage
#define GEMM_SMEM_BYTES (GSTAGES * STAGE_H * 2)    // 75776 B

template<int EPI, typename OutT, bool QKV3>
__global__ __launch_bounds__(128, 2)
void tc_gemm(const __half* __restrict__ A0, const __half* __restrict__ B0,
             const __half* __restrict__ A1, const __half* __restrict__ B1,
             const __half* __restrict__ A2, const __half* __restrict__ B2,
             const float* __restrict__ bias, OutT* __restrict__ C0,
             OutT* __restrict__ C1, OutT* __restrict__ C2,
             int M, int N, int K) {
    extern __shared__ __half smem[];
    const __half* A = A0; const __half* Bm = B0; OutT* C = C0;
    if (QKV3) {
        if (blockIdx.z == 1) { A = A1; Bm = B1; C = C1; }
        else if (blockIdx.z == 2) { A = A2; Bm = B2; C = C2; }
    }
    const int tid = threadIdx.x;
    const int bm = blockIdx.y * 128, bn = blockIdx.x * 128;
    const int warp = tid >> 5, lane = tid & 31;
    const int wm = (warp & 1) * 64;
    const int wn = (warp >> 1) * 64;
    const int g = lane >> 2, t4 = lane & 3;
    const int l16 = lane & 15, lhi = (lane & 16) ? 8 : 0;

    const unsigned sbase = (unsigned)__cvta_generic_to_shared(smem);

    float c[4][8][4];
#pragma unroll
    for (int i = 0; i < 4; i++)
#pragma unroll
        for (int j = 0; j < 8; j++)
#pragma unroll
            for (int r = 0; r < 4; r++) c[i][j][r] = 0.0f;

    // loaders: 128 threads, 4 chunks each for A (512 x 16B) and B (512 x 16B)
    auto load_stage = [&](int buf, int tI) {
        __half* As = smem + buf * STAGE_H;
        __half* Bs = As + 128 * ASTR;
#pragma unroll
        for (int q = 0; q < 4; q++) {
            int ch = tid + 128 * q;
            int ar = ch >> 2, acc_ = (ch & 3) * 8;       // A row, col(halfs)
            cp16(&As[ar * ASTR + acc_], A + (size_t)(bm + ar) * K + tI * 32 + acc_);
            int brr = ch >> 4, bcc = (ch & 15) * 8;      // B row, col(halfs)
            cp16(&Bs[brr * BSTR + bcc], Bm + (size_t)(tI * 32 + brr) * N + bn + bcc);
        }
    };

    const int T = K / 32;
#pragma unroll
    for (int s = 0; s < GSTAGES - 1; s++) {
        load_stage(s, s);
        cp_commit();
    }

    for (int tI = 0; tI < T; tI++) {
        const int buf = tI & (GSTAGES - 1);
        cp_wait<GSTAGES - 2>();
        __syncthreads();
        if (tI + GSTAGES - 1 < T)
            load_stage((tI + GSTAGES - 1) & (GSTAGES - 1), tI + GSTAGES - 1);
        cp_commit();

        const unsigned sA = sbase + 2u * (buf * STAGE_H);
        const unsigned sB = sA + 2u * (128 * ASTR);
#pragma unroll
        for (int step = 0; step < 2; step++) {
            const int k0 = step * 16;
            unsigned af[4][4], bf[8][2];
#pragma unroll
            for (int i = 0; i < 4; i++) {
                unsigned addr = sA + 2u * ((wm + i * 16 + l16) * ASTR + k0 + lhi);
                ldsm4(af[i], addr);
            }
#pragma unroll
            for (int jp = 0; jp < 4; jp++) {
                unsigned addr = sB + 2u * ((k0 + l16) * BSTR + wn + jp * 16 + lhi);
                unsigned r[4];
                ldsm4t(r, addr);
                bf[2 * jp][0] = r[0];     bf[2 * jp][1] = r[1];
                bf[2 * jp + 1][0] = r[2]; bf[2 * jp + 1][1] = r[3];
            }
#pragma unroll
            for (int i = 0; i < 4; i++)
#pragma unroll
                for (int j = 0; j < 8; j++)
                    mma16(c[i][j], af[i], bf[j]);
        }
    }

#pragma unroll
    for (int i = 0; i < 4; i++) {
#pragma unroll
        for (int j = 0; j < 8; j++) {
            const int row0 = bm + wm + i * 16 + g;
            const int col = bn + wn + j * 8 + 2 * t4;
            float v0 = c[i][j][0], v1 = c[i][j][1], v2 = c[i][j][2], v3 = c[i][j][3];
            if (EPI >= 1) {
                float b0 = bias[col], b1 = bias[col + 1];
                v0 += b0; v1 += b1; v2 += b0; v3 += b1;
            }
            if (EPI == 2) {
                v0 *= 1.0f / (1.0f + __expf(-1.702f * v0));
                v1 *= 1.0f / (1.0f + __expf(-1.702f * v1));
                v2 *= 1.0f / (1.0f + __expf(-1.702f * v2));
                v3 *= 1.0f / (1.0f + __expf(-1.702f * v3));
            }
            if (sizeof(OutT) == 2) {
                *(__half2*)((__half*)C + (size_t)row0 * N + col) = __floats2half2_rn(v0, v1);
                *(__half2*)((__half*)C + (size_t)(row0 + 8) * N + col) = __floats2half2_rn(v2, v3);
            } else {
                float2 p0 = {v0, v1}, p1 = {v2, v3};
                *(float2*)((float*)C + (size_t)row0 * N + col) = p0;
                *(float2*)((float*)C + (size_t)(row0 + 8) * N + col) = p1;
            }
        }
    }
}

// ------------------------- fp16 tensor-core flash attention ------------------
// (round 9: 128 q x (b,h), 4 warps x 32 q rows, KB=32 keys, double-buffered)
#define KVSTR 72
#define KB 32

__global__ __launch_bounds__(128)
void attn_tc_kernel(const __half* __restrict__ qp, const __half* __restrict__ kp,
                    const __half* __restrict__ vp, const int* __restrict__ mq,
                    const int* __restrict__ mk, __half* __restrict__ out) {
    __shared__ __half Ks[2][KB * KVSTR];
    __shared__ __half Vs[2][KB * KVSTR];
    __shared__ float kmS[2][KB];

    const int b = blockIdx.z, h = blockIdx.y;
    const int q0 = blockIdx.x * 128;
    const int tid = threadIdx.x;
    const int w = tid >> 5, lane = tid & 31;
    const int g = lane >> 2, t4 = lane & 3;
    const int l16 = lane & 15, lhi = (lane & 16) ? 8 : 0;
    const int l8 = lane & 7, lm = ((lane & 8) ? 8 : 0), ln16 = (lane & 16) ? 8 : 0;

    const unsigned sK0 = (unsigned)__cvta_generic_to_shared(&Ks[0][0]);
    const unsigned sK1 = (unsigned)__cvta_generic_to_shared(&Ks[1][0]);
    const unsigned sV0 = (unsigned)__cvta_generic_to_shared(&Vs[0][0]);
    const unsigned sV1 = (unsigned)__cvta_generic_to_shared(&Vs[1][0]);

    unsigned qa[2][4][4];
#pragma unroll
    for (int i = 0; i < 2; i++) {
        const __half* Qr0 = qp + (size_t)(b * S + q0 + w * 32 + i * 16 + g) * E + h * D;
        const __half* Qr1 = Qr0 + (size_t)8 * E;
#pragma unroll
        for (int s = 0; s < 4; s++) {
            qa[i][s][0] = *(const unsigned*)&Qr0[16 * s + 2 * t4];
            qa[i][s][1] = *(const unsigned*)&Qr1[16 * s + 2 * t4];
            qa[i][s][2] = *(const unsigned*)&Qr0[16 * s + 8 + 2 * t4];
            qa[i][s][3] = *(const unsigned*)&Qr1[16 * s + 8 + 2 * t4];
        }
    }

    float oacc[2][8][4];
#pragma unroll
    for (int i = 0; i < 2; i++)
#pragma unroll
        for (int n = 0; n < 8; n++)
#pragma unroll
            for (int r = 0; r < 4; r++) oacc[i][n][r] = 0.0f;
    float lsum[2][2] = {{0.0f, 0.0f}, {0.0f, 0.0f}};

    auto load_tiles = [&](int kt, int buf) {
        int key = tid >> 2, c8 = (tid & 3) * 16;
        const __half* gk = kp + (size_t)(b * S + kt + key) * E + h * D + c8;
        const __half* gv = vp + (size_t)(b * S + kt + key) * E + h * D + c8;
        cp16(&Ks[buf][key * KVSTR + c8], gk);
        cp16(&Ks[buf][key * KVSTR + c8 + 8], gk + 8);
        cp16(&Vs[buf][key * KVSTR + c8], gv);
        cp16(&Vs[buf][key * KVSTR + c8 + 8], gv + 8);
        if (tid < KB) kmS[buf][tid] = mk[b * S + kt + tid] ? 1.0f : 0.0f;
    };

    load_tiles(0, 0);
    cp_commit();

    for (int kb = 0; kb < S / KB; kb++) {
        const int buf = kb & 1;
        if (kb + 1 < S / KB) {
            load_tiles((kb + 1) * KB, buf ^ 1);
            cp_commit();
            cp_wait<1>();
        } else {
            cp_wait<0>();
        }
        __syncthreads();

        const unsigned sK = buf ? sK1 : sK0;
        const unsigned sV = buf ? sV1 : sV0;

        float sc[2][4][4];
#pragma unroll
        for (int i = 0; i < 2; i++)
#pragma unroll
            for (int j = 0; j < 4; j++)
#pragma unroll
                for (int r = 0; r < 4; r++) sc[i][j][r] = 0.0f;
#pragma unroll
        for (int s = 0; s < 4; s++) {
#pragma unroll
            for (int jp = 0; jp < 2; jp++) {
                unsigned addr = sK + 2u * ((jp * 16 + l8 + ln16) * KVSTR + 16 * s + lm);
                unsigned r[4];
                ldsm4(r, addr);
                unsigned bf0[2] = {r[0], r[1]};
                unsigned bf1[2] = {r[2], r[3]};
#pragma unroll
                for (int i = 0; i < 2; i++) {
                    mma16(sc[i][2 * jp], qa[i][s], bf0);
                    mma16(sc[i][2 * jp + 1], qa[i][s], bf1);
                }
            }
        }

        unsigned pp[2][4][2];
#pragma unroll
        for (int i = 0; i < 2; i++) {
#pragma unroll
            for (int j = 0; j < 4; j++) {
                const int c0 = 8 * j + 2 * t4;
                float m0 = kmS[buf][c0], m1 = kmS[buf][c0 + 1];
                float p0 = __expf(sc[i][j][0] * ATT_SCALE) * m0;
                float p1 = __expf(sc[i][j][1] * ATT_SCALE) * m1;
                float p2 = __expf(sc[i][j][2] * ATT_SCALE) * m0;
                float p3 = __expf(sc[i][j][3] * ATT_SCALE) * m1;
                lsum[i][0] += p0 + p1;
                lsum[i][1] += p2 + p3;
                pp[i][j][0] = h2u(__floats2half2_rn(p0, p1));
                pp[i][j][1] = h2u(__floats2half2_rn(p2, p3));
            }
        }

#pragma unroll
        for (int s = 0; s < 2; s++) {
            unsigned pa[2][4];
#pragma unroll
            for (int i = 0; i < 2; i++) {
                pa[i][0] = pp[i][2 * s][0]; pa[i][1] = pp[i][2 * s][1];
                pa[i][2] = pp[i][2 * s + 1][0]; pa[i][3] = pp[i][2 * s + 1][1];
            }
#pragma unroll
            for (int np = 0; np < 4; np++) {
                unsigned addr = sV + 2u * ((16 * s + l16) * KVSTR + np * 16 + lhi);
                unsigned r[4];
                ldsm4t(r, addr);
                unsigned bf0[2] = {r[0], r[1]};
                unsigned bf1[2] = {r[2], r[3]};
#pragma unroll
                for (int i = 0; i < 2; i++) {
                    mma16(oacc[i][2 * np], pa[i], bf0);
                    mma16(oacc[i][2 * np + 1], pa[i], bf1);
                }
            }
        }
        __syncthreads();
    }

#pragma unroll
    for (int i = 0; i < 2; i++) {
        float l0 = lsum[i][0], l1 = lsum[i][1];
        l0 += __shfl_xor_sync(0xffffffffu, l0, 1);
        l0 += __shfl_xor_sync(0xffffffffu, l0, 2);
        l1 += __shfl_xor_sync(0xffffffffu, l1, 1);
        l1 += __shfl_xor_sync(0xffffffffu, l1, 2);

        const int row0 = b * S + q0 + w * 32 + i * 16 + g;
        const float inv0 = mq[row0] ? 1.0f / l0 : 0.0f;
        const float inv1 = mq[row0 + 8] ? 1.0f / l1 : 0.0f;
        __half* o0 = out + (size_t)row0 * E + h * D;
        __half* o1 = o0 + (size_t)8 * E;
#pragma unroll
        for (int n = 0; n < 8; n++) {
            const int c0 = 8 * n + 2 * t4;
            *(__half2*)(o0 + c0) = __floats2half2_rn(oacc[i][n][0] * inv0, oacc[i][n][1] * inv0);
            *(__half2*)(o1 + c0) = __floats2half2_rn(oacc[i][n][2] * inv1, oacc[i][n][3] * inv1);
        }
    }
}

// ------------------------- layernorm + mask + residual -----------------------
template<int MODE, typename OutT>
__global__ __launch_bounds__(256)
void ln_kernel(const float* __restrict__ x, const float* __restrict__ res,
               const float* __restrict__ g, const float* __restrict__ bb,
               const int* __restrict__ mask, OutT* __restrict__ out) {
    __shared__ float s1[256], s2[256];
    const int row = blockIdx.x;
    const int tid = threadIdx.x;
    const float* xr = x + (size_t)row * E;
    const float* rr = res + (size_t)row * E;
    float v[4];
    float s = 0.0f, sq = 0.0f;
#pragma unroll
    for (int i = 0; i < 4; i++) {
        int c = tid + i * 256;
        float t = xr[c];
        if (MODE == 1) t += rr[c];
        v[i] = t; s += t; sq += t * t;
    }
    s1[tid] = s; s2[tid] = sq;
    __syncthreads();
    for (int off = 128; off > 0; off >>= 1) {
        if (tid < off) { s1[tid] += s1[tid + off]; s2[tid] += s2[tid + off]; }
        __syncthreads();
    }
    float mu = s1[0] * (1.0f / E);
    float var = s2[0] * (1.0f / E) - mu * mu;
    float rstd = rsqrtf(var + 1e-5f);
    float mkf = mask[row] ? 1.0f : 0.0f;
#pragma unroll
    for (int i = 0; i < 4; i++) {
        int c = tid + i * 256;
        float y = (v[i] - mu) * rstd * g[c] + bb[c];
        float o = (MODE == 0) ? (y * mkf + rr[c]) : (y * mkf);
        if (sizeof(OutT) == 2) ((__half*)out)[(size_t)row * E + c] = __float2half(o);
        else                   ((float*)out)[(size_t)row * E + c] = o;
    }
}

// ------------------------- launch -------------------------------------------
extern "C" void kernel_launch(void* const* d_in, const int* in_sizes, int n_in,
                              void* d_out, int out_size) {
    const float* value = (const float*)d_in[0];
    const float* key   = (const float*)d_in[1];
    const float* query = (const float*)d_in[2];
    const void*  mask_k_raw = d_in[3];
    const void*  mask_q_raw = d_in[4];
    const float* Wv = (const float*)d_in[5];
    const float* Wk = (const float*)d_in[6];
    const float* Wq = (const float*)d_in[7];
    const float* Wo = (const float*)d_in[8];
    const float* ln0_g = (const float*)d_in[9];
    const float* ln0_b = (const float*)d_in[10];
    const float* W1 = (const float*)d_in[11];
    const float* b1 = (const float*)d_in[12];
    const float* W2 = (const float*)d_in[13];
    const float* b2 = (const float*)d_in[14];
    const float* ln1_g = (const float*)d_in[15];
    const float* ln1_b = (const float*)d_in[16];
    float* out = (float*)d_out;

    __half *qh, *kh, *vh, *Wqh, *Wkh, *Wvh, *Woh, *W1h, *W2h;
    __half *qph, *kph, *vph, *attnh, *hh, *g1h;
    float *att, *ff;
    int *mq, *mk;
    cudaGetSymbolAddress((void**)&qh,   g_qh);
    cudaGetSymbolAddress((void**)&kh,   g_kh);
    cudaGetSymbolAddress((void**)&vh,   g_vh);
    cudaGetSymbolAddress((void**)&Wqh,  g_Wqh);
    cudaGetSymbolAddress((void**)&Wkh,  g_Wkh);
    cudaGetSymbolAddress((void**)&Wvh,  g_Wvh);
    cudaGetSymbolAddress((void**)&Woh,  g_Woh);
    cudaGetSymbolAddress((void**)&W1h,  g_W1h);
    cudaGetSymbolAddress((void**)&W2h,  g_W2h);
    cudaGetSymbolAddress((void**)&qph,  g_qph);
    cudaGetSymbolAddress((void**)&kph,  g_kph);
    cudaGetSymbolAddress((void**)&vph,  g_vph);
    cudaGetSymbolAddress((void**)&attnh,g_attnh);
    cudaGetSymbolAddress((void**)&hh,   g_hh);
    cudaGetSymbolAddress((void**)&g1h,  g_g1h);
    cudaGetSymbolAddress((void**)&att,  g_att);
    cudaGetSymbolAddress((void**)&ff,   g_ff);
    cudaGetSymbolAddress((void**)&mq,   g_mq);
    cudaGetSymbolAddress((void**)&mk,   g_mk);

    cudaFuncSetAttribute(tc_gemm<0, __half, true>,  cudaFuncAttributeMaxDynamicSharedMemorySize, GEMM_SMEM_BYTES);
    cudaFuncSetAttribute(tc_gemm<0, float, false>,  cudaFuncAttributeMaxDynamicSharedMemorySize, GEMM_SMEM_BYTES);
    cudaFuncSetAttribute(tc_gemm<1, float, false>,  cudaFuncAttributeMaxDynamicSharedMemorySize, GEMM_SMEM_BYTES);
    cudaFuncSetAttribute(tc_gemm<2, __half, false>, cudaFuncAttributeMaxDynamicSharedMemorySize, GEMM_SMEM_BYTES);

    mask_convert2_kernel<<<1, 256>>>(mask_k_raw, mk, mask_q_raw, mq, NROWS);

    f2h_all_kernel<<<1184, 256>>>(query, qh, key, kh, value, vh,
                                  Wq, Wqh, Wk, Wkh, Wv, Wvh, Wo, Woh,
                                  W1, W1h, W2, W2h);

    dim3 gE3(E / 128, NROWS / 128, 3);    // fused Q/K/V projections
    dim3 gE(E / 128, NROWS / 128);
    dim3 gF(FFDIM / 128, NROWS / 128);

    tc_gemm<0, __half, true><<<gE3, 128, GEMM_SMEM_BYTES>>>(
        qh, Wqh, kh, Wkh, vh, Wvh, nullptr, qph, kph, vph, NROWS, E, E);

    attn_tc_kernel<<<dim3(S / 128, H, B), 128>>>(qph, kph, vph, mq, mk, attnh);

    tc_gemm<0, float, false><<<gE, 128, GEMM_SMEM_BYTES>>>(
        attnh, Woh, nullptr, nullptr, nullptr, nullptr, nullptr,
        att, nullptr, nullptr, NROWS, E, E);

    ln_kernel<0, __half><<<NROWS, 256>>>(att, query, ln0_g, ln0_b, mq, hh);

    tc_gemm<2, __half, false><<<gF, 128, GEMM_SMEM_BYTES>>>(
        hh, W1h, nullptr, nullptr, nullptr, nullptr, b1,
        g1h, nullptr, nullptr, NROWS, FFDIM, E);
    tc_gemm<1, float, false><<<gE, 128, GEMM_SMEM_BYTES>>>(
        g1h, W2h, nullptr, nullptr, nullptr, nullptr, b2,
        ff, nullptr, nullptr, NROWS, E, FFDIM);

    ln_kernel<1, float><<<NROWS, 256>>>(ff, query, ln1_g, ln1_b, mq, out);
}